// round 13
// baseline (speedup 1.0000x reference)
#include <cuda_runtime.h>
#include <cuda_bf16.h>
#include <math.h>
#include <stdint.h>

#define N_ATOMS 4096
#define N_EDGES 131072
#define EMBED 64
#define HID 128
#define TP_IN 1152
#define NBINS 2048
#define D_LO 0.4f
#define D_HI 6.0f

// ---------------- scratch ----------------
__device__ __align__(16) float g_pre[N_ATOMS * TP_IN];
__device__ __align__(16) float g_upd[N_ATOMS * HID];
__device__ __align__(16) float g_q[N_ATOMS * HID];
__device__ __align__(16) __nv_bfloat16 g_k16[N_ATOMS * HID];
__device__ __align__(16) __nv_bfloat16 g_v16[N_ATOMS * HID];
__device__ __align__(16) float g_att[N_ATOMS * HID];
__device__ __align__(16) float g_tpw[TP_IN * HID];
__device__ __align__(16) float g_wqkvT[HID * 3 * HID];
__device__ __align__(16) float g_woutT[HID * HID];
__device__ __align__(16) float g_radtab[(NBINS + 8) * HID];
__device__ __align__(16) float4 g_evp[N_EDGES];  // permuted edge payload {vx,vy,vz,d}
__device__ __align__(16) int g_count[N_ATOMS];   // zeroed by epi each launch
__device__ int g_offset[N_ATOMS + 1];
__device__ int g_cursor[N_ATOMS];

// ---------------- helpers ----------------
__device__ __forceinline__ void mma_tf32(float* d, const uint32_t* a, const uint32_t* b) {
    asm volatile(
        "mma.sync.aligned.m16n8k8.row.col.f32.tf32.tf32.f32 "
        "{%0,%1,%2,%3},{%4,%5,%6,%7},{%8,%9},{%0,%1,%2,%3};\n"
        : "+f"(d[0]), "+f"(d[1]), "+f"(d[2]), "+f"(d[3])
        : "r"(a[0]), "r"(a[1]), "r"(a[2]), "r"(a[3]), "r"(b[0]), "r"(b[1]));
}
__device__ __forceinline__ void mma_bf16(float* d, const uint32_t* a, const uint32_t* b) {
    asm volatile(
        "mma.sync.aligned.m16n8k16.row.col.f32.bf16.bf16.f32 "
        "{%0,%1,%2,%3},{%4,%5,%6,%7},{%8,%9},{%0,%1,%2,%3};\n"
        : "+f"(d[0]), "+f"(d[1]), "+f"(d[2]), "+f"(d[3])
        : "r"(a[0]), "r"(a[1]), "r"(a[2]), "r"(a[3]), "r"(b[0]), "r"(b[1]));
}
__device__ __forceinline__ uint32_t rna_bits(float x) {
    uint32_t r;
    asm("cvt.rna.tf32.f32 %0, %1;" : "=r"(r) : "f"(x));
    return r;
}
__device__ __forceinline__ float rna_tf32(float x) {
    return __uint_as_float(rna_bits(x));
}
__device__ __forceinline__ uint32_t packbf(float lo, float hi) {
    uint32_t r;
    asm("cvt.rn.bf16x2.f32 %0, %1, %2;" : "=r"(r) : "f"(hi), "f"(lo));
    return r;
}
__device__ __forceinline__ float fexp2(float x) {
    float r;
    asm("ex2.approx.ftz.f32 %0, %1;" : "=f"(r) : "f"(x));
    return r;
}
__device__ __forceinline__ void cp16(uint32_t dst, const void* src) {
    asm volatile("cp.async.cg.shared.global [%0], [%1], 16;\n" :: "r"(dst), "l"(src));
}
__device__ __forceinline__ void ldmatrix_x2_trans(uint32_t& r0, uint32_t& r1, uint32_t addr) {
    asm volatile("ldmatrix.sync.aligned.m8n8.x2.trans.shared.b16 {%0,%1}, [%2];"
                 : "=r"(r0), "=r"(r1) : "r"(addr));
}
#define CP_COMMIT asm volatile("cp.async.commit_group;\n" ::: "memory")
#define CP_WAIT0  asm volatile("cp.async.wait_group 0;\n" ::: "memory")

// =============== mega kernel A: prep | radtab | hist (independent) ===========
__global__ void __launch_bounds__(256) megaA_kernel(
    const float* __restrict__ tpw, const float* __restrict__ win,
    const float* __restrict__ wout,
    const float* __restrict__ rw1, const float* __restrict__ rb1,
    const float* __restrict__ rw2, const float* __restrict__ rb2,
    const int* __restrict__ dst) {
    __shared__ float w1s[8 * 64];
    __shared__ float w2s[64 * 128];
    __shared__ float b1s[64];
    __shared__ float b2s[128];
    __shared__ float r1s[8][64];
    const int b = blockIdx.x;
    const int t = threadIdx.x;

    if (b < 576) {
        int i = b * 256 + t;
        int rp = i >> 7;
        int c = i & 127;
        int s = rp >> 7;
        int h = rp & 127;
        int row;
        if (s == 0)      row = h;
        else if (s <= 3) row = 128 + h * 3 + (s - 1);
        else             row = 512 + h * 5 + (s - 4);
        g_tpw[i] = rna_tf32(tpw[row * HID + c]);
    } else if (b < 768) {
        int i = (b - 576) * 256 + t;
        int d = i / 384, j = i % 384;
        g_wqkvT[i] = win[j * HID + d];
    } else if (b < 832) {
        int i = (b - 768) * 256 + t;
        int d = i >> 7, j = i & 127;
        g_woutT[i] = wout[j * HID + d];
    } else if (b < 1089) {       // radial table
        for (int i = t; i < 512; i += 256) w1s[i] = rw1[i];
        for (int i = t; i < 8192; i += 256) w2s[i] = rw2[i];
        if (t < 64) b1s[t] = rb1[t];
        if (t < 128) b2s[t] = rb2[t];
        __syncthreads();
        int w = t >> 5, lane = t & 31;
        int bin = (b - 832) * 8 + w;
        if (bin > NBINS) return;
        const float hstep = (D_HI - D_LO) / (float)NBINS;
        const float FP = 3.14159265358979323846f / 6.0f;
        float d = D_LO + bin * hstep;
        float cut = 0.5f * (cosf(d * FP) + 1.f) * (d < 6.0f ? 1.f : 0.f);
        float invd = cut / d;
        float rbf[8];
#pragma unroll
        for (int i = 0; i < 8; i++) rbf[i] = sinf(d * (FP * (i + 1))) * invd;
        float a0 = b1s[lane], a1 = b1s[lane + 32];
#pragma unroll
        for (int i = 0; i < 8; i++) {
            a0 += rbf[i] * w1s[i * 64 + lane];
            a1 += rbf[i] * w1s[i * 64 + lane + 32];
        }
        a0 = a0 / (1.f + __expf(-a0));
        a1 = a1 / (1.f + __expf(-a1));
        r1s[w][lane] = a0;
        r1s[w][lane + 32] = a1;
        __syncwarp();
        float r2[4];
#pragma unroll
        for (int k = 0; k < 4; k++) r2[k] = b2s[k * 32 + lane];
#pragma unroll 8
        for (int j = 0; j < 64; j++) {
            float rj = r1s[w][j];
#pragma unroll
            for (int k = 0; k < 4; k++) r2[k] += rj * w2s[j * 128 + k * 32 + lane];
        }
#pragma unroll
        for (int k = 0; k < 4; k++) {
            float v = r2[k];
            v = v / (1.f + __expf(-v));
            g_radtab[bin * HID + k * 32 + lane] = v;
        }
    } else {
        int i = (b - 1089) * 256 + t;
        if (i < N_EDGES) atomicAdd(&g_count[dst[i]], 1);
    }
}

// ---------------- hierarchical warp scan ----------------
__global__ void __launch_bounds__(1024) scan_kernel() {
    __shared__ int wsum[32];
    int t = threadIdx.x, lane = t & 31, wid = t >> 5;
    int4 v = *(const int4*)(g_count + t * 4);
    int s0 = v.x, s1 = s0 + v.y, s2 = s1 + v.z, s3 = s2 + v.w;
    int ws = s3;
#pragma unroll
    for (int off = 1; off < 32; off <<= 1) {
        int n = __shfl_up_sync(0xffffffffu, ws, off);
        if (lane >= off) ws += n;
    }
    if (lane == 31) wsum[wid] = ws;
    __syncthreads();
    if (wid == 0) {
        int x = wsum[lane];
#pragma unroll
        for (int off = 1; off < 32; off <<= 1) {
            int n = __shfl_up_sync(0xffffffffu, x, off);
            if (lane >= off) x += n;
        }
        wsum[lane] = x;
    }
    __syncthreads();
    int base = (wid ? wsum[wid - 1] : 0) + (ws - s3);
    g_offset[t * 4 + 1] = base + s0;
    g_offset[t * 4 + 2] = base + s1;
    g_offset[t * 4 + 3] = base + s2;
    g_offset[t * 4 + 4] = base + s3;
    g_cursor[t * 4 + 0] = base;
    g_cursor[t * 4 + 1] = base + s0;
    g_cursor[t * 4 + 2] = base + s1;
    g_cursor[t * 4 + 3] = base + s2;
    if (t == 0) g_offset[0] = 0;
}

// ---------------- scatter: permute full edge payload ----------------
__global__ void scatter_kernel(const int* __restrict__ dst,
                               const float* __restrict__ ev,
                               const float* __restrict__ el) {
    int i = blockIdx.x * blockDim.x + threadIdx.x;
    if (i < N_EDGES) {
        float vx = ev[i * 3 + 0];
        float vy = ev[i * 3 + 1];
        float vz = ev[i * 3 + 2];
        float d = el[i];
        int p = atomicAdd(&g_cursor[dst[i]], 1);
        g_evp[p] = make_float4(vx, vy, vz, d);
    }
}

// ------- edge aggregation: 2 warps per atom; contiguous payload loads -------
__global__ void __launch_bounds__(128) edge_agg_kernel() {
    __shared__ float red[2][4][9][32];
    int t = threadIdx.x;
    int w = t >> 5, lane = t & 31;
    int pair = w >> 1, h = w & 1;
    int atom = blockIdx.x * 2 + pair;
    int start = g_offset[atom];
    int end = g_offset[atom + 1];
    int n = end - start;
    int halfn = (n + 1) >> 1;
    int s0 = start + h * halfn;
    int e0 = min(end, s0 + halfn);

    float acc[4][9];
#pragma unroll
    for (int k = 0; k < 4; k++)
#pragma unroll
        for (int s = 0; s < 9; s++) acc[k][s] = 0.f;

    const float INV_H = (float)NBINS / (D_HI - D_LO);

    int idx = s0;
    for (; idx + 2 <= e0; idx += 2) {
        float4 p0v = __ldg(g_evp + idx);
        float4 p1v = __ldg(g_evp + idx + 1);
        float vx0 = p0v.x, vy0 = p0v.y, vz0 = p0v.z, d0 = p0v.w;
        float vx1 = p1v.x, vy1 = p1v.y, vz1 = p1v.z, d1 = p1v.w;

        float tt0 = (d0 - D_LO) * INV_H;
        float tt1 = (d1 - D_LO) * INV_H;
        int i00 = min(max((int)tt0, 0), NBINS - 1);
        int i01 = min(max((int)tt1, 0), NBINS - 1);
        float f0 = tt0 - (float)i00;
        float f1 = tt1 - (float)i01;
        const float* r0p = g_radtab + (size_t)i00 * HID;
        const float* r1p = g_radtab + (size_t)i01 * HID;

        float r0 = sqrtf(vx0 * vx0 + vy0 * vy0 + vz0 * vz0) + 1e-8f;
        float r1 = sqrtf(vx1 * vx1 + vy1 * vy1 + vz1 * vz1) + 1e-8f;
        float iv0 = 1.f / r0, iv1 = 1.f / r1;
        float x0 = vx0 * iv0, y0 = vy0 * iv0, z0 = vz0 * iv0;
        float x1 = vx1 * iv1, y1 = vy1 * iv1, z1 = vz1 * iv1;
        float sh0[9], sh1[9];
        sh0[0] = 1.f; sh0[1] = y0; sh0[2] = z0; sh0[3] = x0;
        sh0[4] = 3.f * z0 * z0 - 1.f; sh0[5] = x0 * z0; sh0[6] = y0 * z0;
        sh0[7] = x0 * y0; sh0[8] = x0 * x0 - y0 * y0;
        sh1[0] = 1.f; sh1[1] = y1; sh1[2] = z1; sh1[3] = x1;
        sh1[4] = 3.f * z1 * z1 - 1.f; sh1[5] = x1 * z1; sh1[6] = y1 * z1;
        sh1[7] = x1 * y1; sh1[8] = x1 * x1 - y1 * y1;

#pragma unroll
        for (int k = 0; k < 4; k++) {
            int c = k * 32 + lane;
            float lo0 = r0p[c], hi0 = r0p[c + HID];
            float lo1 = r1p[c], hi1 = r1p[c + HID];
            float ra0 = fmaf(f0, hi0 - lo0, lo0);
            float ra1 = fmaf(f1, hi1 - lo1, lo1);
#pragma unroll
            for (int s = 0; s < 9; s++)
                acc[k][s] += ra0 * sh0[s] + ra1 * sh1[s];
        }
    }
    if (idx < e0) {
        float4 pv = __ldg(g_evp + idx);
        float vx = pv.x, vy = pv.y, vz = pv.z, d = pv.w;
        float r = sqrtf(vx * vx + vy * vy + vz * vz) + 1e-8f;
        float inv = 1.f / r;
        float x = vx * inv, y = vy * inv, z = vz * inv;
        float sh[9];
        sh[0] = 1.f; sh[1] = y; sh[2] = z; sh[3] = x;
        sh[4] = 3.f * z * z - 1.f; sh[5] = x * z; sh[6] = y * z;
        sh[7] = x * y; sh[8] = x * x - y * y;
        float tt = (d - D_LO) * INV_H;
        int i0 = min(max((int)tt, 0), NBINS - 1);
        float f = tt - (float)i0;
        const float* r0p = g_radtab + (size_t)i0 * HID;
#pragma unroll
        for (int k = 0; k < 4; k++) {
            int c = k * 32 + lane;
            float lo = r0p[c], hi = r0p[c + HID];
            float ra = fmaf(f, hi - lo, lo);
#pragma unroll
            for (int s = 0; s < 9; s++) acc[k][s] += ra * sh[s];
        }
    }

    if (h == 1) {
#pragma unroll
        for (int k = 0; k < 4; k++)
#pragma unroll
            for (int s = 0; s < 9; s++) red[pair][k][s][lane] = acc[k][s];
    }
    __syncthreads();
    if (h == 0) {
#pragma unroll
        for (int k = 0; k < 4; k++)
#pragma unroll
            for (int s = 0; s < 9; s++) {
                float v = acc[k][s] + red[pair][k][s][lane];
                g_pre[(size_t)atom * TP_IN + s * 128 + k * 32 + lane] = v;
            }
    }
}

// ======= FUSED: tp-GEMM (tf32 mma) -> upd MLP -> qkv, 32 atoms/block ========
__global__ void __launch_bounds__(256) tpupd_kernel(
    const float* __restrict__ tpb,
    const int* __restrict__ an, const float* __restrict__ embed,
    const float* __restrict__ mw1, const float* __restrict__ mb1,
    const float* __restrict__ mw2, const float* __restrict__ mb2,
    const float* __restrict__ bqkv) {
    __shared__ __align__(16) char sraw[47232];
    float* As = (float*)sraw;                    // 2 x 640 floats
    float* Bs = (float*)(sraw + 5120);           // 2 x 2176 floats
    float* t1 = (float*)sraw;                    // 32 x 128 (phase 2)
    float* comb = (float*)(sraw + 22528);        // 32 x 192
    int* ans = (int*)(sraw + 47104);

    const int t = threadIdx.x;
    const int warp = t >> 5, lane = t & 31;
    const int g = lane >> 2, tg = lane & 3;
    const int rows0 = blockIdx.x * 32;
    const int rloc = (warp & 1) * 16;
    const int c0 = (warp >> 1) * 32;

    uint32_t as_base = (uint32_t)__cvta_generic_to_shared(As);
    uint32_t bs_base = (uint32_t)__cvta_generic_to_shared(Bs);

    if (t < 32) ans[t] = an[rows0 + t];
    __syncthreads();
    for (int i = t; i < 2048; i += 256) {
        int a = i >> 6, d = i & 63;
        comb[a * 192 + d] = embed[ans[a] * 64 + d];
    }

    float C[4][4];
#pragma unroll
    for (int nn = 0; nn < 4; nn++)
#pragma unroll
        for (int i = 0; i < 4; i++) C[nn][i] = 0.f;

    if (t < 128) {
        int r = t >> 2, ch = (t & 3) * 4;
        cp16(as_base + (r * 20 + ch) * 4, g_pre + (size_t)(rows0 + r) * TP_IN + ch);
    }
#pragma unroll
    for (int i = t; i < 512; i += 256) {
        int kr = i >> 5, c = (i & 31) * 4;
        cp16(bs_base + (kr * 136 + c) * 4, g_tpw + (size_t)kr * HID + c);
    }
    CP_COMMIT;

    for (int kc = 0; kc < 72; kc++) {
        CP_WAIT0;
        __syncthreads();
        int buf = kc & 1;
        if (kc + 1 < 72) {
            int nb = buf ^ 1;
            if (t < 128) {
                int r = t >> 2, ch = (t & 3) * 4;
                cp16(as_base + (nb * 640 + r * 20 + ch) * 4,
                     g_pre + (size_t)(rows0 + r) * TP_IN + (kc + 1) * 16 + ch);
            }
#pragma unroll
            for (int i = t; i < 512; i += 256) {
                int kr = i >> 5, c = (i & 31) * 4;
                cp16(bs_base + (nb * 2176 + kr * 136 + c) * 4,
                     g_tpw + (size_t)((kc + 1) * 16 + kr) * HID + c);
            }
            CP_COMMIT;
        }
#pragma unroll
        for (int k8 = 0; k8 < 2; k8++) {
            int k0 = k8 * 8;
            uint32_t a4[4];
            a4[0] = rna_bits(As[buf * 640 + (rloc + g) * 20 + k0 + tg]);
            a4[1] = rna_bits(As[buf * 640 + (rloc + g + 8) * 20 + k0 + tg]);
            a4[2] = rna_bits(As[buf * 640 + (rloc + g) * 20 + k0 + tg + 4]);
            a4[3] = rna_bits(As[buf * 640 + (rloc + g + 8) * 20 + k0 + tg + 4]);
#pragma unroll
            for (int nn = 0; nn < 4; nn++) {
                uint32_t b[2];
                b[0] = __float_as_uint(Bs[buf * 2176 + (k0 + tg) * 136 + c0 + nn * 8 + g]);
                b[1] = __float_as_uint(Bs[buf * 2176 + (k0 + tg + 4) * 136 + c0 + nn * 8 + g]);
                mma_tf32(C[nn], a4, b);
            }
        }
        __syncthreads();
    }

    {
        int a0 = rloc + g, a1 = a0 + 8;
        int gr0 = rows0 + a0, gr1 = rows0 + a1;
        float deg0 = (float)(g_offset[gr0 + 1] - g_offset[gr0]);
        float deg1 = (float)(g_offset[gr1 + 1] - g_offset[gr1]);
#pragma unroll
        for (int nn = 0; nn < 4; nn++) {
            int col = c0 + nn * 8 + 2 * tg;
            float b0 = tpb[col], b1 = tpb[col + 1];
            comb[a0 * 192 + 64 + col] = C[nn][0] + deg0 * b0;
            comb[a0 * 192 + 64 + col + 1] = C[nn][1] + deg0 * b1;
            comb[a1 * 192 + 64 + col] = C[nn][2] + deg1 * b0;
            comb[a1 * 192 + 64 + col + 1] = C[nn][3] + deg1 * b1;
        }
    }
    __syncthreads();

    const int col = t & 127;
    const int half = t >> 7;
    float acc[16];
#pragma unroll
    for (int a = 0; a < 16; a++) acc[a] = 0.f;
    for (int d = 0; d < 192; d++) {
        float wv = mw1[d * HID + col];
#pragma unroll
        for (int a = 0; a < 16; a++) acc[a] += comb[(half * 16 + a) * 192 + d] * wv;
    }
    float b1v = mb1[col];
#pragma unroll
    for (int a = 0; a < 16; a++) {
        float v = acc[a] + b1v;
        t1[(half * 16 + a) * 128 + col] = v / (1.f + __expf(-v));
    }
    __syncthreads();
#pragma unroll
    for (int a = 0; a < 16; a++) acc[a] = 0.f;
    for (int d = 0; d < 128; d++) {
        float wv = mw2[d * HID + col];
#pragma unroll
        for (int a = 0; a < 16; a++) acc[a] += t1[(half * 16 + a) * 128 + d] * wv;
    }
    float b2v = mb2[col];
#pragma unroll
    for (int a = 0; a < 16; a++) {
        int aa = half * 16 + a;
        float v = acc[a] + b2v;
        comb[aa * 128 + col] = v;
        g_upd[(size_t)(rows0 + aa) * HID + col] = v;
    }
    __syncthreads();

    float* upds = comb;
#pragma unroll
    for (int cb = 0; cb < 3; cb++) {
        float q[16];
#pragma unroll
        for (int a = 0; a < 16; a++) q[a] = 0.f;
        for (int d = 0; d < 128; d++) {
            float wv = g_wqkvT[d * 384 + cb * 128 + col];
#pragma unroll
            for (int a = 0; a < 16; a++) q[a] += upds[(half * 16 + a) * 128 + d] * wv;
        }
        float bb = bqkv[cb * 128 + col];
#pragma unroll
        for (int a = 0; a < 16; a++) {
            int aa = half * 16 + a;
            float s = q[a] + bb;
            size_t row = (size_t)(rows0 + aa) * HID;
            if (cb == 0)      g_q[row + col] = s;
            else if (cb == 1) g_k16[row + col] = __float2bfloat16_rn(s);
            else              g_v16[row + col] = __float2bfloat16_rn(s);
        }
    }
}

// ---------------- bf16 mma flash attention — 128-key tiles, single wave -----
__global__ void __launch_bounds__(256) attn_mma_kernel() {
    __shared__ __align__(16) __nv_bfloat16 Ks[2][128 * 40];
    __shared__ __align__(16) __nv_bfloat16 Vs[2][128 * 40];
    const int t = threadIdx.x;
    const int warp = t >> 5, lane = t & 31;
    const int g = lane >> 2, tg = lane & 3;
    const int head = blockIdx.y;
    const int q0 = blockIdx.x * 128 + warp * 16;
    const float SC = 0.17677669529663687f * 1.4426950408889634f;

    uint32_t ks_base = (uint32_t)__cvta_generic_to_shared(Ks);
    uint32_t vs_base = (uint32_t)__cvta_generic_to_shared(Vs);

    uint32_t qb[2][4];
#pragma unroll
    for (int kk2 = 0; kk2 < 2; kk2++) {
        const float* qp = g_q + (size_t)(q0 + g) * HID + head * 32 + kk2 * 16;
        const float* qp8 = qp + 8 * HID;
        float2 f0 = *(const float2*)(qp + 2 * tg);
        float2 f1 = *(const float2*)(qp8 + 2 * tg);
        float2 f2 = *(const float2*)(qp + 2 * tg + 8);
        float2 f3 = *(const float2*)(qp8 + 2 * tg + 8);
        qb[kk2][0] = packbf(f0.x * SC, f0.y * SC);
        qb[kk2][1] = packbf(f1.x * SC, f1.y * SC);
        qb[kk2][2] = packbf(f2.x * SC, f2.y * SC);
        qb[kk2][3] = packbf(f3.x * SC, f3.y * SC);
    }

    float O[4][4];
#pragma unroll
    for (int nn = 0; nn < 4; nn++)
#pragma unroll
        for (int i = 0; i < 4; i++) O[nn][i] = 0.f;
    float m0 = -1e30f, m1 = -1e30f, l0 = 0.f, l1 = 0.f;

#pragma unroll
    for (int i = t; i < 1024; i += 256) {
        int key = i >> 3, part = i & 7;
        int kv = part >> 2;
        int ch = (part & 3) * 16;
        const char* src = (const char*)(kv ? g_v16 : g_k16) +
                          (size_t)key * 256 + head * 64 + ch;
        uint32_t dst = (kv ? vs_base : ks_base) + key * 80 + ch;
        cp16(dst, src);
    }
    CP_COMMIT;

    for (int kt = 0; kt < 32; kt++) {
        CP_WAIT0;
        __syncthreads();
        int buf = kt & 1;
        if (kt + 1 < 32) {
            int nb = buf ^ 1;
#pragma unroll
            for (int i = t; i < 1024; i += 256) {
                int key = i >> 3, part = i & 7;
                int kv = part >> 2;
                int ch = (part & 3) * 16;
                const char* src = (const char*)(kv ? g_v16 : g_k16) +
                                  (size_t)((kt + 1) * 128 + key) * 256 + head * 64 + ch;
                uint32_t dst = (kv ? vs_base : ks_base) + nb * 10240 + key * 80 + ch;
                cp16(dst, src);
            }
            CP_COMMIT;
        }
        const char* Kb = (const char*)Ks + buf * 10240;

        float S[16][4];
#pragma unroll
        for (int nn = 0; nn < 16; nn++)
#pragma unroll
            for (int i = 0; i < 4; i++) S[nn][i] = 0.f;
#pragma unroll
        for (int kk2 = 0; kk2 < 2; kk2++) {
#pragma unroll
            for (int nn = 0; nn < 16; nn++) {
                const uint32_t* kw = (const uint32_t*)(Kb + (nn * 8 + g) * 80);
                uint32_t b[2];
                b[0] = kw[kk2 * 8 + tg];
                b[1] = kw[kk2 * 8 + tg + 4];
                mma_bf16(S[nn], qb[kk2], b);
            }
        }

        float mx0 = fmaxf(S[0][0], S[0][1]);
        float mx1 = fmaxf(S[0][2], S[0][3]);
#pragma unroll
        for (int nn = 1; nn < 16; nn++) {
            mx0 = fmaxf(mx0, fmaxf(S[nn][0], S[nn][1]));
            mx1 = fmaxf(mx1, fmaxf(S[nn][2], S[nn][3]));
        }
        mx0 = fmaxf(mx0, __shfl_xor_sync(0xffffffffu, mx0, 1));
        mx0 = fmaxf(mx0, __shfl_xor_sync(0xffffffffu, mx0, 2));
        mx1 = fmaxf(mx1, __shfl_xor_sync(0xffffffffu, mx1, 1));
        mx1 = fmaxf(mx1, __shfl_xor_sync(0xffffffffu, mx1, 2));
        float nm0 = fmaxf(m0, mx0), nm1 = fmaxf(m1, mx1);
        float c0 = fexp2(m0 - nm0), c1 = fexp2(m1 - nm1);
        m0 = nm0; m1 = nm1;
        l0 *= c0; l1 *= c1;
#pragma unroll
        for (int nn = 0; nn < 4; nn++) {
            O[nn][0] *= c0; O[nn][1] *= c0;
            O[nn][2] *= c1; O[nn][3] *= c1;
        }
#pragma unroll
        for (int nn = 0; nn < 16; nn++) {
            float p0 = fexp2(S[nn][0] - m0);
            float p1 = fexp2(S[nn][1] - m0);
            float p2 = fexp2(S[nn][2] - m1);
            float p3 = fexp2(S[nn][3] - m1);
            l0 += p0 + p1;
            l1 += p2 + p3;
            S[nn][0] = p0; S[nn][1] = p1; S[nn][2] = p2; S[nn][3] = p3;
        }

#pragma unroll
        for (int kkv = 0; kkv < 8; kkv++) {
            uint32_t a[4];
            a[0] = packbf(S[2 * kkv][0], S[2 * kkv][1]);
            a[1] = packbf(S[2 * kkv][2], S[2 * kkv][3]);
            a[2] = packbf(S[2 * kkv + 1][0], S[2 * kkv + 1][1]);
            a[3] = packbf(S[2 * kkv + 1][2], S[2 * kkv + 1][3]);
            uint32_t rowaddr = vs_base + buf * 10240 + (kkv * 16 + (lane & 15)) * 80;
#pragma unroll
            for (int nn = 0; nn < 4; nn++) {
                uint32_t b[2];
                ldmatrix_x2_trans(b[0], b[1], rowaddr + nn * 16);
                mma_bf16(O[nn], a, b);
            }
        }
        __syncthreads();
    }

    l0 += __shfl_xor_sync(0xffffffffu, l0, 1);
    l0 += __shfl_xor_sync(0xffffffffu, l0, 2);
    l1 += __shfl_xor_sync(0xffffffffu, l1, 1);
    l1 += __shfl_xor_sync(0xffffffffu, l1, 2);
    float i0 = 1.f / l0, i1 = 1.f / l1;
#pragma unroll
    for (int nn = 0; nn < 4; nn++) {
        *(float2*)(g_att + (size_t)(q0 + g) * HID + head * 32 + nn * 8 + 2 * tg) =
            make_float2(O[nn][0] * i0, O[nn][1] * i0);
        *(float2*)(g_att + (size_t)(q0 + g + 8) * HID + head * 32 + nn * 8 + 2 * tg) =
            make_float2(O[nn][2] * i1, O[nn][3] * i1);
    }
}

// ---------------- epilogue: 128 blocks x 256 thr x 32 atoms (single wave) ---
__global__ void __launch_bounds__(256) epi_kernel(
    const float* __restrict__ bout_att,
    const float* __restrict__ gw, const float* __restrict__ gb,
    const float* __restrict__ ow, const float* __restrict__ ob,
    float* __restrict__ out) {
    __shared__ float att[32][128];
    __shared__ float upd[32][128];
    __shared__ float osh[32][128];
    int t = threadIdx.x;
    int base = blockIdx.x * 32;
    for (int i = t; i < 4096; i += 256) {
        int a = i >> 7, d = i & 127;
        att[a][d] = g_att[(size_t)(base + a) * HID + d];
        upd[a][d] = g_upd[(size_t)(base + a) * HID + d];
    }
    if (t < 32) g_count[base + t] = 0;
    __syncthreads();
    const int col = t & 127;
    const int half = t >> 7;
    float ap[16];
#pragma unroll
    for (int a = 0; a < 16; a++) ap[a] = 0.f;
    for (int d = 0; d < 128; d++) {
        float wv = g_woutT[d * HID + col];
#pragma unroll
        for (int a = 0; a < 16; a++) ap[a] += att[half * 16 + a][d] * wv;
    }
    float ba = bout_att[col];
    float gacc[16];
#pragma unroll
    for (int a = 0; a < 16; a++) gacc[a] = 0.f;
    for (int d = 0; d < 128; d++) {
        float wv = gw[d * HID + col];
#pragma unroll
        for (int a = 0; a < 16; a++) gacc[a] += upd[half * 16 + a][d] * wv;
    }
    float bg = gb[col];
#pragma unroll
    for (int a = 0; a < 16; a++) {
        int aa = half * 16 + a;
        float gg = 1.f / (1.f + __expf(-(gacc[a] + bg)));
        osh[aa][col] = gg * (ap[a] + ba) + (1.f - gg) * upd[aa][col];
    }
    __syncthreads();
    float f[16];
#pragma unroll
    for (int a = 0; a < 16; a++) f[a] = 0.f;
    for (int d = 0; d < 128; d++) {
        float wv = ow[d * HID + col];
#pragma unroll
        for (int a = 0; a < 16; a++) f[a] += osh[half * 16 + a][d] * wv;
    }
    float bo = ob[col];
#pragma unroll
    for (int a = 0; a < 16; a++)
        out[(size_t)(base + half * 16 + a) * HID + col] = f[a] + bo;
}

// ---------------- launch ----------------
extern "C" void kernel_launch(void* const* d_in, const int* in_sizes, int n_in,
                              void* d_out, int out_size) {
    const int* an = (const int*)d_in[0];
    const int* ei = (const int*)d_in[2];
    const float* ev = (const float*)d_in[3];
    const float* el = (const float*)d_in[4];
    const float* embed = (const float*)d_in[5];
    const float* rw1 = (const float*)d_in[6];
    const float* rb1 = (const float*)d_in[7];
    const float* rw2 = (const float*)d_in[8];
    const float* rb2 = (const float*)d_in[9];
    const float* tpw = (const float*)d_in[10];
    const float* tpb = (const float*)d_in[11];
    const float* mw1 = (const float*)d_in[12];
    const float* mb1 = (const float*)d_in[13];
    const float* mw2 = (const float*)d_in[14];
    const float* mb2 = (const float*)d_in[15];
    const float* win = (const float*)d_in[16];
    const float* bin = (const float*)d_in[17];
    const float* wout = (const float*)d_in[18];
    const float* bout = (const float*)d_in[19];
    const float* gw = (const float*)d_in[20];
    const float* gb = (const float*)d_in[21];
    const float* ow = (const float*)d_in[22];
    const float* obv = (const float*)d_in[23];
    float* out = (float*)d_out;

    const int* dst = ei + N_EDGES;

    megaA_kernel<<<1601, 256>>>(tpw, win, wout, rw1, rb1, rw2, rb2, dst);
    scan_kernel<<<1, 1024>>>();
    scatter_kernel<<<512, 256>>>(dst, ev, el);
    edge_agg_kernel<<<2048, 128>>>();
    tpupd_kernel<<<128, 256>>>(tpb, an, embed, mw1, mb1, mw2, mb2, bin);
    attn_mma_kernel<<<dim3(32, 4), 256>>>();
    epi_kernel<<<128, 256>>>(bout, gw, gb, ow, obv, out);
}

// round 15
// speedup vs baseline: 1.0016x; 1.0016x over previous
#include <cuda_runtime.h>
#include <cuda_bf16.h>
#include <math.h>
#include <stdint.h>

#define N_ATOMS 4096
#define N_EDGES 131072
#define EMBED 64
#define HID 128
#define TP_IN 1152
#define NBINS 2048
#define D_LO 0.4f
#define D_HI 6.0f

// ---------------- scratch ----------------
__device__ __align__(16) float g_pre[N_ATOMS * TP_IN];
__device__ __align__(16) float g_upd[N_ATOMS * HID];
__device__ __align__(16) float g_q[N_ATOMS * HID];
__device__ __align__(16) __nv_bfloat16 g_k16[N_ATOMS * HID];
__device__ __align__(16) __nv_bfloat16 g_v16[N_ATOMS * HID];
__device__ __align__(16) float g_att[N_ATOMS * HID];
__device__ __align__(16) float g_tpw[TP_IN * HID];
__device__ __align__(16) float g_wqkvT[HID * 3 * HID];
__device__ __align__(16) float g_woutT[HID * HID];
__device__ __align__(16) float g_radtab[(NBINS + 8) * HID];
__device__ __align__(16) float4 g_evp[N_EDGES];  // permuted edge payload {vx,vy,vz,d}
__device__ __align__(16) int g_count[N_ATOMS];   // zeroed by epi each launch
__device__ int g_offset[N_ATOMS + 1];
__device__ int g_cursor[N_ATOMS];

// ---------------- helpers ----------------
__device__ __forceinline__ void mma_tf32(float* d, const uint32_t* a, const uint32_t* b) {
    asm volatile(
        "mma.sync.aligned.m16n8k8.row.col.f32.tf32.tf32.f32 "
        "{%0,%1,%2,%3},{%4,%5,%6,%7},{%8,%9},{%0,%1,%2,%3};\n"
        : "+f"(d[0]), "+f"(d[1]), "+f"(d[2]), "+f"(d[3])
        : "r"(a[0]), "r"(a[1]), "r"(a[2]), "r"(a[3]), "r"(b[0]), "r"(b[1]));
}
__device__ __forceinline__ void mma_bf16(float* d, const uint32_t* a, const uint32_t* b) {
    asm volatile(
        "mma.sync.aligned.m16n8k16.row.col.f32.bf16.bf16.f32 "
        "{%0,%1,%2,%3},{%4,%5,%6,%7},{%8,%9},{%0,%1,%2,%3};\n"
        : "+f"(d[0]), "+f"(d[1]), "+f"(d[2]), "+f"(d[3])
        : "r"(a[0]), "r"(a[1]), "r"(a[2]), "r"(a[3]), "r"(b[0]), "r"(b[1]));
}
__device__ __forceinline__ uint32_t rna_bits(float x) {
    uint32_t r;
    asm("cvt.rna.tf32.f32 %0, %1;" : "=r"(r) : "f"(x));
    return r;
}
__device__ __forceinline__ float rna_tf32(float x) {
    return __uint_as_float(rna_bits(x));
}
__device__ __forceinline__ uint32_t packbf(float lo, float hi) {
    uint32_t r;
    asm("cvt.rn.bf16x2.f32 %0, %1, %2;" : "=r"(r) : "f"(hi), "f"(lo));
    return r;
}
__device__ __forceinline__ float fexp2(float x) {
    float r;
    asm("ex2.approx.ftz.f32 %0, %1;" : "=f"(r) : "f"(x));
    return r;
}
__device__ __forceinline__ void cp16(uint32_t dst, const void* src) {
    asm volatile("cp.async.cg.shared.global [%0], [%1], 16;\n" :: "r"(dst), "l"(src));
}
__device__ __forceinline__ void ldmatrix_x4(uint32_t* r, uint32_t addr) {
    asm volatile("ldmatrix.sync.aligned.m8n8.x4.shared.b16 {%0,%1,%2,%3}, [%4];"
                 : "=r"(r[0]), "=r"(r[1]), "=r"(r[2]), "=r"(r[3]) : "r"(addr));
}
__device__ __forceinline__ void ldmatrix_x4_trans(uint32_t* r, uint32_t addr) {
    asm volatile("ldmatrix.sync.aligned.m8n8.x4.trans.shared.b16 {%0,%1,%2,%3}, [%4];"
                 : "=r"(r[0]), "=r"(r[1]), "=r"(r[2]), "=r"(r[3]) : "r"(addr));
}
#define CP_COMMIT asm volatile("cp.async.commit_group;\n" ::: "memory")
#define CP_WAIT0  asm volatile("cp.async.wait_group 0;\n" ::: "memory")

// =============== mega kernel A: prep | radtab | hist (independent) ===========
__global__ void __launch_bounds__(256) megaA_kernel(
    const float* __restrict__ tpw, const float* __restrict__ win,
    const float* __restrict__ wout,
    const float* __restrict__ rw1, const float* __restrict__ rb1,
    const float* __restrict__ rw2, const float* __restrict__ rb2,
    const int* __restrict__ dst) {
    __shared__ float w1s[8 * 64];
    __shared__ float w2s[64 * 128];
    __shared__ float b1s[64];
    __shared__ float b2s[128];
    __shared__ float r1s[8][64];
    const int b = blockIdx.x;
    const int t = threadIdx.x;

    if (b < 576) {
        int i = b * 256 + t;
        int rp = i >> 7;
        int c = i & 127;
        int s = rp >> 7;
        int h = rp & 127;
        int row;
        if (s == 0)      row = h;
        else if (s <= 3) row = 128 + h * 3 + (s - 1);
        else             row = 512 + h * 5 + (s - 4);
        g_tpw[i] = rna_tf32(tpw[row * HID + c]);
    } else if (b < 768) {
        int i = (b - 576) * 256 + t;
        int d = i / 384, j = i % 384;
        g_wqkvT[i] = win[j * HID + d];
    } else if (b < 832) {
        int i = (b - 768) * 256 + t;
        int d = i >> 7, j = i & 127;
        g_woutT[i] = wout[j * HID + d];
    } else if (b < 1089) {       // radial table
        for (int i = t; i < 512; i += 256) w1s[i] = rw1[i];
        for (int i = t; i < 8192; i += 256) w2s[i] = rw2[i];
        if (t < 64) b1s[t] = rb1[t];
        if (t < 128) b2s[t] = rb2[t];
        __syncthreads();
        int w = t >> 5, lane = t & 31;
        int bin = (b - 832) * 8 + w;
        if (bin > NBINS) return;
        const float hstep = (D_HI - D_LO) / (float)NBINS;
        const float FP = 3.14159265358979323846f / 6.0f;
        float d = D_LO + bin * hstep;
        float cut = 0.5f * (cosf(d * FP) + 1.f) * (d < 6.0f ? 1.f : 0.f);
        float invd = cut / d;
        float rbf[8];
#pragma unroll
        for (int i = 0; i < 8; i++) rbf[i] = sinf(d * (FP * (i + 1))) * invd;
        float a0 = b1s[lane], a1 = b1s[lane + 32];
#pragma unroll
        for (int i = 0; i < 8; i++) {
            a0 += rbf[i] * w1s[i * 64 + lane];
            a1 += rbf[i] * w1s[i * 64 + lane + 32];
        }
        a0 = a0 / (1.f + __expf(-a0));
        a1 = a1 / (1.f + __expf(-a1));
        r1s[w][lane] = a0;
        r1s[w][lane + 32] = a1;
        __syncwarp();
        float r2[4];
#pragma unroll
        for (int k = 0; k < 4; k++) r2[k] = b2s[k * 32 + lane];
#pragma unroll 8
        for (int j = 0; j < 64; j++) {
            float rj = r1s[w][j];
#pragma unroll
            for (int k = 0; k < 4; k++) r2[k] += rj * w2s[j * 128 + k * 32 + lane];
        }
#pragma unroll
        for (int k = 0; k < 4; k++) {
            float v = r2[k];
            v = v / (1.f + __expf(-v));
            g_radtab[bin * HID + k * 32 + lane] = v;
        }
    } else {
        int i = (b - 1089) * 256 + t;
        if (i < N_EDGES) atomicAdd(&g_count[dst[i]], 1);
    }
}

// ---------------- hierarchical warp scan ----------------
__global__ void __launch_bounds__(1024) scan_kernel() {
    __shared__ int wsum[32];
    int t = threadIdx.x, lane = t & 31, wid = t >> 5;
    int4 v = *(const int4*)(g_count + t * 4);
    int s0 = v.x, s1 = s0 + v.y, s2 = s1 + v.z, s3 = s2 + v.w;
    int ws = s3;
#pragma unroll
    for (int off = 1; off < 32; off <<= 1) {
        int n = __shfl_up_sync(0xffffffffu, ws, off);
        if (lane >= off) ws += n;
    }
    if (lane == 31) wsum[wid] = ws;
    __syncthreads();
    if (wid == 0) {
        int x = wsum[lane];
#pragma unroll
        for (int off = 1; off < 32; off <<= 1) {
            int n = __shfl_up_sync(0xffffffffu, x, off);
            if (lane >= off) x += n;
        }
        wsum[lane] = x;
    }
    __syncthreads();
    int base = (wid ? wsum[wid - 1] : 0) + (ws - s3);
    g_offset[t * 4 + 1] = base + s0;
    g_offset[t * 4 + 2] = base + s1;
    g_offset[t * 4 + 3] = base + s2;
    g_offset[t * 4 + 4] = base + s3;
    g_cursor[t * 4 + 0] = base;
    g_cursor[t * 4 + 1] = base + s0;
    g_cursor[t * 4 + 2] = base + s1;
    g_cursor[t * 4 + 3] = base + s2;
    if (t == 0) g_offset[0] = 0;
}

// ---------------- scatter: permute full edge payload ----------------
__global__ void scatter_kernel(const int* __restrict__ dst,
                               const float* __restrict__ ev,
                               const float* __restrict__ el) {
    int i = blockIdx.x * blockDim.x + threadIdx.x;
    if (i < N_EDGES) {
        float vx = ev[i * 3 + 0];
        float vy = ev[i * 3 + 1];
        float vz = ev[i * 3 + 2];
        float d = el[i];
        int p = atomicAdd(&g_cursor[dst[i]], 1);
        g_evp[p] = make_float4(vx, vy, vz, d);
    }
}

// ------- edge aggregation: 2 warps per atom; contiguous payload loads -------
__global__ void __launch_bounds__(128) edge_agg_kernel() {
    __shared__ float red[2][4][9][32];
    int t = threadIdx.x;
    int w = t >> 5, lane = t & 31;
    int pair = w >> 1, h = w & 1;
    int atom = blockIdx.x * 2 + pair;
    int start = g_offset[atom];
    int end = g_offset[atom + 1];
    int n = end - start;
    int halfn = (n + 1) >> 1;
    int s0 = start + h * halfn;
    int e0 = min(end, s0 + halfn);

    float acc[4][9];
#pragma unroll
    for (int k = 0; k < 4; k++)
#pragma unroll
        for (int s = 0; s < 9; s++) acc[k][s] = 0.f;

    const float INV_H = (float)NBINS / (D_HI - D_LO);

    int idx = s0;
    for (; idx + 2 <= e0; idx += 2) {
        float4 p0v = __ldg(g_evp + idx);
        float4 p1v = __ldg(g_evp + idx + 1);
        float vx0 = p0v.x, vy0 = p0v.y, vz0 = p0v.z, d0 = p0v.w;
        float vx1 = p1v.x, vy1 = p1v.y, vz1 = p1v.z, d1 = p1v.w;

        float tt0 = (d0 - D_LO) * INV_H;
        float tt1 = (d1 - D_LO) * INV_H;
        int i00 = min(max((int)tt0, 0), NBINS - 1);
        int i01 = min(max((int)tt1, 0), NBINS - 1);
        float f0 = tt0 - (float)i00;
        float f1 = tt1 - (float)i01;
        const float* r0p = g_radtab + (size_t)i00 * HID;
        const float* r1p = g_radtab + (size_t)i01 * HID;

        float r0 = sqrtf(vx0 * vx0 + vy0 * vy0 + vz0 * vz0) + 1e-8f;
        float r1 = sqrtf(vx1 * vx1 + vy1 * vy1 + vz1 * vz1) + 1e-8f;
        float iv0 = 1.f / r0, iv1 = 1.f / r1;
        float x0 = vx0 * iv0, y0 = vy0 * iv0, z0 = vz0 * iv0;
        float x1 = vx1 * iv1, y1 = vy1 * iv1, z1 = vz1 * iv1;
        float sh0[9], sh1[9];
        sh0[0] = 1.f; sh0[1] = y0; sh0[2] = z0; sh0[3] = x0;
        sh0[4] = 3.f * z0 * z0 - 1.f; sh0[5] = x0 * z0; sh0[6] = y0 * z0;
        sh0[7] = x0 * y0; sh0[8] = x0 * x0 - y0 * y0;
        sh1[0] = 1.f; sh1[1] = y1; sh1[2] = z1; sh1[3] = x1;
        sh1[4] = 3.f * z1 * z1 - 1.f; sh1[5] = x1 * z1; sh1[6] = y1 * z1;
        sh1[7] = x1 * y1; sh1[8] = x1 * x1 - y1 * y1;

#pragma unroll
        for (int k = 0; k < 4; k++) {
            int c = k * 32 + lane;
            float lo0 = r0p[c], hi0 = r0p[c + HID];
            float lo1 = r1p[c], hi1 = r1p[c + HID];
            float ra0 = fmaf(f0, hi0 - lo0, lo0);
            float ra1 = fmaf(f1, hi1 - lo1, lo1);
#pragma unroll
            for (int s = 0; s < 9; s++)
                acc[k][s] += ra0 * sh0[s] + ra1 * sh1[s];
        }
    }
    if (idx < e0) {
        float4 pv = __ldg(g_evp + idx);
        float vx = pv.x, vy = pv.y, vz = pv.z, d = pv.w;
        float r = sqrtf(vx * vx + vy * vy + vz * vz) + 1e-8f;
        float inv = 1.f / r;
        float x = vx * inv, y = vy * inv, z = vz * inv;
        float sh[9];
        sh[0] = 1.f; sh[1] = y; sh[2] = z; sh[3] = x;
        sh[4] = 3.f * z * z - 1.f; sh[5] = x * z; sh[6] = y * z;
        sh[7] = x * y; sh[8] = x * x - y * y;
        float tt = (d - D_LO) * INV_H;
        int i0 = min(max((int)tt, 0), NBINS - 1);
        float f = tt - (float)i0;
        const float* r0p = g_radtab + (size_t)i0 * HID;
#pragma unroll
        for (int k = 0; k < 4; k++) {
            int c = k * 32 + lane;
            float lo = r0p[c], hi = r0p[c + HID];
            float ra = fmaf(f, hi - lo, lo);
#pragma unroll
            for (int s = 0; s < 9; s++) acc[k][s] += ra * sh[s];
        }
    }

    if (h == 1) {
#pragma unroll
        for (int k = 0; k < 4; k++)
#pragma unroll
            for (int s = 0; s < 9; s++) red[pair][k][s][lane] = acc[k][s];
    }
    __syncthreads();
    if (h == 0) {
#pragma unroll
        for (int k = 0; k < 4; k++)
#pragma unroll
            for (int s = 0; s < 9; s++) {
                float v = acc[k][s] + red[pair][k][s][lane];
                g_pre[(size_t)atom * TP_IN + s * 128 + k * 32 + lane] = v;
            }
    }
}

// ======= FUSED: tp-GEMM (tf32 mma) -> upd MLP -> qkv, 32 atoms/block ========
__global__ void __launch_bounds__(256) tpupd_kernel(
    const float* __restrict__ tpb,
    const int* __restrict__ an, const float* __restrict__ embed,
    const float* __restrict__ mw1, const float* __restrict__ mb1,
    const float* __restrict__ mw2, const float* __restrict__ mb2,
    const float* __restrict__ bqkv) {
    __shared__ __align__(16) char sraw[47232];
    float* As = (float*)sraw;                    // 2 x 640 floats
    float* Bs = (float*)(sraw + 5120);           // 2 x 2176 floats
    float* t1 = (float*)sraw;                    // 32 x 128 (phase 2)
    float* comb = (float*)(sraw + 22528);        // 32 x 192
    int* ans = (int*)(sraw + 47104);

    const int t = threadIdx.x;
    const int warp = t >> 5, lane = t & 31;
    const int g = lane >> 2, tg = lane & 3;
    const int rows0 = blockIdx.x * 32;
    const int rloc = (warp & 1) * 16;
    const int c0 = (warp >> 1) * 32;

    uint32_t as_base = (uint32_t)__cvta_generic_to_shared(As);
    uint32_t bs_base = (uint32_t)__cvta_generic_to_shared(Bs);

    if (t < 32) ans[t] = an[rows0 + t];
    __syncthreads();
    for (int i = t; i < 2048; i += 256) {
        int a = i >> 6, d = i & 63;
        comb[a * 192 + d] = embed[ans[a] * 64 + d];
    }

    float C[4][4];
#pragma unroll
    for (int nn = 0; nn < 4; nn++)
#pragma unroll
        for (int i = 0; i < 4; i++) C[nn][i] = 0.f;

    if (t < 128) {
        int r = t >> 2, ch = (t & 3) * 4;
        cp16(as_base + (r * 20 + ch) * 4, g_pre + (size_t)(rows0 + r) * TP_IN + ch);
    }
#pragma unroll
    for (int i = t; i < 512; i += 256) {
        int kr = i >> 5, c = (i & 31) * 4;
        cp16(bs_base + (kr * 136 + c) * 4, g_tpw + (size_t)kr * HID + c);
    }
    CP_COMMIT;

    for (int kc = 0; kc < 72; kc++) {
        CP_WAIT0;
        __syncthreads();
        int buf = kc & 1;
        if (kc + 1 < 72) {
            int nb = buf ^ 1;
            if (t < 128) {
                int r = t >> 2, ch = (t & 3) * 4;
                cp16(as_base + (nb * 640 + r * 20 + ch) * 4,
                     g_pre + (size_t)(rows0 + r) * TP_IN + (kc + 1) * 16 + ch);
            }
#pragma unroll
            for (int i = t; i < 512; i += 256) {
                int kr = i >> 5, c = (i & 31) * 4;
                cp16(bs_base + (nb * 2176 + kr * 136 + c) * 4,
                     g_tpw + (size_t)((kc + 1) * 16 + kr) * HID + c);
            }
            CP_COMMIT;
        }
#pragma unroll
        for (int k8 = 0; k8 < 2; k8++) {
            int k0 = k8 * 8;
            uint32_t a4[4];
            a4[0] = rna_bits(As[buf * 640 + (rloc + g) * 20 + k0 + tg]);
            a4[1] = rna_bits(As[buf * 640 + (rloc + g + 8) * 20 + k0 + tg]);
            a4[2] = rna_bits(As[buf * 640 + (rloc + g) * 20 + k0 + tg + 4]);
            a4[3] = rna_bits(As[buf * 640 + (rloc + g + 8) * 20 + k0 + tg + 4]);
#pragma unroll
            for (int nn = 0; nn < 4; nn++) {
                uint32_t b[2];
                b[0] = __float_as_uint(Bs[buf * 2176 + (k0 + tg) * 136 + c0 + nn * 8 + g]);
                b[1] = __float_as_uint(Bs[buf * 2176 + (k0 + tg + 4) * 136 + c0 + nn * 8 + g]);
                mma_tf32(C[nn], a4, b);
            }
        }
        // trailing sync removed: next iteration's head sync orders buffer reuse
    }

    {
        int a0 = rloc + g, a1 = a0 + 8;
        int gr0 = rows0 + a0, gr1 = rows0 + a1;
        float deg0 = (float)(g_offset[gr0 + 1] - g_offset[gr0]);
        float deg1 = (float)(g_offset[gr1 + 1] - g_offset[gr1]);
#pragma unroll
        for (int nn = 0; nn < 4; nn++) {
            int col = c0 + nn * 8 + 2 * tg;
            float b0 = tpb[col], b1 = tpb[col + 1];
            comb[a0 * 192 + 64 + col] = C[nn][0] + deg0 * b0;
            comb[a0 * 192 + 64 + col + 1] = C[nn][1] + deg0 * b1;
            comb[a1 * 192 + 64 + col] = C[nn][2] + deg1 * b0;
            comb[a1 * 192 + 64 + col + 1] = C[nn][3] + deg1 * b1;
        }
    }
    __syncthreads();

    const int col = t & 127;
    const int half = t >> 7;
    float acc[16];
#pragma unroll
    for (int a = 0; a < 16; a++) acc[a] = 0.f;
    for (int d = 0; d < 192; d++) {
        float wv = mw1[d * HID + col];
#pragma unroll
        for (int a = 0; a < 16; a++) acc[a] += comb[(half * 16 + a) * 192 + d] * wv;
    }
    float b1v = mb1[col];
#pragma unroll
    for (int a = 0; a < 16; a++) {
        float v = acc[a] + b1v;
        t1[(half * 16 + a) * 128 + col] = v / (1.f + __expf(-v));
    }
    __syncthreads();
#pragma unroll
    for (int a = 0; a < 16; a++) acc[a] = 0.f;
    for (int d = 0; d < 128; d++) {
        float wv = mw2[d * HID + col];
#pragma unroll
        for (int a = 0; a < 16; a++) acc[a] += t1[(half * 16 + a) * 128 + d] * wv;
    }
    float b2v = mb2[col];
#pragma unroll
    for (int a = 0; a < 16; a++) {
        int aa = half * 16 + a;
        float v = acc[a] + b2v;
        comb[aa * 128 + col] = v;
        g_upd[(size_t)(rows0 + aa) * HID + col] = v;
    }
    __syncthreads();

    float* upds = comb;
#pragma unroll
    for (int cb = 0; cb < 3; cb++) {
        float q[16];
#pragma unroll
        for (int a = 0; a < 16; a++) q[a] = 0.f;
        for (int d = 0; d < 128; d++) {
            float wv = g_wqkvT[d * 384 + cb * 128 + col];
#pragma unroll
            for (int a = 0; a < 16; a++) q[a] += upds[(half * 16 + a) * 128 + d] * wv;
        }
        float bb = bqkv[cb * 128 + col];
#pragma unroll
        for (int a = 0; a < 16; a++) {
            int aa = half * 16 + a;
            float s = q[a] + bb;
            size_t row = (size_t)(rows0 + aa) * HID;
            if (cb == 0)      g_q[row + col] = s;
            else if (cb == 1) g_k16[row + col] = __float2bfloat16_rn(s);
            else              g_v16[row + col] = __float2bfloat16_rn(s);
        }
    }
}

// ---------------- bf16 mma flash attention — 128-key tiles, single wave -----
// K frags via ldmatrix.x4 (non-trans), V via ldmatrix.x4.trans; one sync/tile.
__global__ void __launch_bounds__(256) attn_mma_kernel() {
    __shared__ __align__(16) __nv_bfloat16 Ks[2][128 * 40];
    __shared__ __align__(16) __nv_bfloat16 Vs[2][128 * 40];
    const int t = threadIdx.x;
    const int warp = t >> 5, lane = t & 31;
    const int g = lane >> 2, tg = lane & 3;
    const int head = blockIdx.y;
    const int q0 = blockIdx.x * 128 + warp * 16;
    const float SC = 0.17677669529663687f * 1.4426950408889634f;

    uint32_t ks_base = (uint32_t)__cvta_generic_to_shared(Ks);
    uint32_t vs_base = (uint32_t)__cvta_generic_to_shared(Vs);

    uint32_t qb[2][4];
#pragma unroll
    for (int kk2 = 0; kk2 < 2; kk2++) {
        const float* qp = g_q + (size_t)(q0 + g) * HID + head * 32 + kk2 * 16;
        const float* qp8 = qp + 8 * HID;
        float2 f0 = *(const float2*)(qp + 2 * tg);
        float2 f1 = *(const float2*)(qp8 + 2 * tg);
        float2 f2 = *(const float2*)(qp + 2 * tg + 8);
        float2 f3 = *(const float2*)(qp8 + 2 * tg + 8);
        qb[kk2][0] = packbf(f0.x * SC, f0.y * SC);
        qb[kk2][1] = packbf(f1.x * SC, f1.y * SC);
        qb[kk2][2] = packbf(f2.x * SC, f2.y * SC);
        qb[kk2][3] = packbf(f3.x * SC, f3.y * SC);
    }

    float O[4][4];
#pragma unroll
    for (int nn = 0; nn < 4; nn++)
#pragma unroll
        for (int i = 0; i < 4; i++) O[nn][i] = 0.f;
    float m0 = -1e30f, m1 = -1e30f, l0 = 0.f, l1 = 0.f;

#pragma unroll
    for (int i = t; i < 1024; i += 256) {
        int key = i >> 3, part = i & 7;
        int kv = part >> 2;
        int ch = (part & 3) * 16;
        const char* src = (const char*)(kv ? g_v16 : g_k16) +
                          (size_t)key * 256 + head * 64 + ch;
        uint32_t dst = (kv ? vs_base : ks_base) + key * 80 + ch;
        cp16(dst, src);
    }
    CP_COMMIT;

    // ldmatrix lane-address components (constant across tiles)
    const int klane_row = lane & 7;          // row within 8-key group
    const int klane_khalf = (lane >> 3) & 1; // k-half (0/8 dims -> +16B)
    const int klane_nn = lane >> 4;          // nn sub-tile (+8 keys)
    const int vlane_row = lane & 15;
    const int vlane_nn = lane >> 4;

    for (int kt = 0; kt < 32; kt++) {
        CP_WAIT0;
        __syncthreads();
        int buf = kt & 1;
        if (kt + 1 < 32) {
            int nb = buf ^ 1;
#pragma unroll
            for (int i = t; i < 1024; i += 256) {
                int key = i >> 3, part = i & 7;
                int kv = part >> 2;
                int ch = (part & 3) * 16;
                const char* src = (const char*)(kv ? g_v16 : g_k16) +
                                  (size_t)((kt + 1) * 128 + key) * 256 + head * 64 + ch;
                uint32_t dst = (kv ? vs_base : ks_base) + nb * 10240 + key * 80 + ch;
                cp16(dst, src);
            }
            CP_COMMIT;
        }

        float S[16][4];
#pragma unroll
        for (int nn = 0; nn < 16; nn++)
#pragma unroll
            for (int i = 0; i < 4; i++) S[nn][i] = 0.f;
        // QK: ldmatrix.x4 fetches B-frags for key-tiles (2*nn2, 2*nn2+1)
        uint32_t kaddr_base = ks_base + buf * 10240 +
                              (klane_row + klane_nn * 8) * 80 + klane_khalf * 16;
#pragma unroll
        for (int kk2 = 0; kk2 < 2; kk2++) {
#pragma unroll
            for (int nn2 = 0; nn2 < 8; nn2++) {
                uint32_t b4[4];
                ldmatrix_x4(b4, kaddr_base + nn2 * (16 * 80) + kk2 * 32);
                mma_bf16(S[2 * nn2], qb[kk2], b4);
                mma_bf16(S[2 * nn2 + 1], qb[kk2], b4 + 2);
            }
        }

        float mx0 = fmaxf(S[0][0], S[0][1]);
        float mx1 = fmaxf(S[0][2], S[0][3]);
#pragma unroll
        for (int nn = 1; nn < 16; nn++) {
            mx0 = fmaxf(mx0, fmaxf(S[nn][0], S[nn][1]));
            mx1 = fmaxf(mx1, fmaxf(S[nn][2], S[nn][3]));
        }
        mx0 = fmaxf(mx0, __shfl_xor_sync(0xffffffffu, mx0, 1));
        mx0 = fmaxf(mx0, __shfl_xor_sync(0xffffffffu, mx0, 2));
        mx1 = fmaxf(mx1, __shfl_xor_sync(0xffffffffu, mx1, 1));
        mx1 = fmaxf(mx1, __shfl_xor_sync(0xffffffffu, mx1, 2));
        float nm0 = fmaxf(m0, mx0), nm1 = fmaxf(m1, mx1);
        float c0 = fexp2(m0 - nm0), c1 = fexp2(m1 - nm1);
        m0 = nm0; m1 = nm1;
        l0 *= c0; l1 *= c1;
#pragma unroll
        for (int nn = 0; nn < 4; nn++) {
            O[nn][0] *= c0; O[nn][1] *= c0;
            O[nn][2] *= c1; O[nn][3] *= c1;
        }
#pragma unroll
        for (int nn = 0; nn < 16; nn++) {
            float p0 = fexp2(S[nn][0] - m0);
            float p1 = fexp2(S[nn][1] - m0);
            float p2 = fexp2(S[nn][2] - m1);
            float p3 = fexp2(S[nn][3] - m1);
            l0 += p0 + p1;
            l1 += p2 + p3;
            S[nn][0] = p0; S[nn][1] = p1; S[nn][2] = p2; S[nn][3] = p3;
        }

        // PV: ldmatrix.x4.trans fetches V-frags for output tiles (2*nn2, 2*nn2+1)
        uint32_t vaddr_base = vs_base + buf * 10240 + vlane_row * 80 + vlane_nn * 16;
#pragma unroll
        for (int kkv = 0; kkv < 8; kkv++) {
            uint32_t a[4];
            a[0] = packbf(S[2 * kkv][0], S[2 * kkv][1]);
            a[1] = packbf(S[2 * kkv][2], S[2 * kkv][3]);
            a[2] = packbf(S[2 * kkv + 1][0], S[2 * kkv + 1][1]);
            a[3] = packbf(S[2 * kkv + 1][2], S[2 * kkv + 1][3]);
            uint32_t rowaddr = vaddr_base + kkv * (16 * 80);
#pragma unroll
            for (int nn2 = 0; nn2 < 2; nn2++) {
                uint32_t b4[4];
                ldmatrix_x4_trans(b4, rowaddr + nn2 * 32);
                mma_bf16(O[2 * nn2], a, b4);
                mma_bf16(O[2 * nn2 + 1], a, b4 + 2);
            }
        }
        // trailing sync removed: next iteration's head sync orders buffer reuse
    }

    l0 += __shfl_xor_sync(0xffffffffu, l0, 1);
    l0 += __shfl_xor_sync(0xffffffffu, l0, 2);
    l1 += __shfl_xor_sync(0xffffffffu, l1, 1);
    l1 += __shfl_xor_sync(0xffffffffu, l1, 2);
    float i0 = 1.f / l0, i1 = 1.f / l1;
#pragma unroll
    for (int nn = 0; nn < 4; nn++) {
        *(float2*)(g_att + (size_t)(q0 + g) * HID + head * 32 + nn * 8 + 2 * tg) =
            make_float2(O[nn][0] * i0, O[nn][1] * i0);
        *(float2*)(g_att + (size_t)(q0 + g + 8) * HID + head * 32 + nn * 8 + 2 * tg) =
            make_float2(O[nn][2] * i1, O[nn][3] * i1);
    }
}

// ---------------- epilogue: 128 blocks x 256 thr x 32 atoms (single wave) ---
__global__ void __launch_bounds__(256) epi_kernel(
    const float* __restrict__ bout_att,
    const float* __restrict__ gw, const float* __restrict__ gb,
    const float* __restrict__ ow, const float* __restrict__ ob,
    float* __restrict__ out) {
    __shared__ float att[32][128];
    __shared__ float upd[32][128];
    __shared__ float osh[32][128];
    int t = threadIdx.x;
    int base = blockIdx.x * 32;
    for (int i = t; i < 4096; i += 256) {
        int a = i >> 7, d = i & 127;
        att[a][d] = g_att[(size_t)(base + a) * HID + d];
        upd[a][d] = g_upd[(size_t)(base + a) * HID + d];
    }
    if (t < 32) g_count[base + t] = 0;
    __syncthreads();
    const int col = t & 127;
    const int half = t >> 7;
    float ap[16];
#pragma unroll
    for (int a = 0; a < 16; a++) ap[a] = 0.f;
    for (int d = 0; d < 128; d++) {
        float wv = g_woutT[d * HID + col];
#pragma unroll
        for (int a = 0; a < 16; a++) ap[a] += att[half * 16 + a][d] * wv;
    }
    float ba = bout_att[col];
    float gacc[16];
#pragma unroll
    for (int a = 0; a < 16; a++) gacc[a] = 0.f;
    for (int d = 0; d < 128; d++) {
        float wv = gw[d * HID + col];
#pragma unroll
        for (int a = 0; a < 16; a++) gacc[a] += upd[half * 16 + a][d] * wv;
    }
    float bg = gb[col];
#pragma unroll
    for (int a = 0; a < 16; a++) {
        int aa = half * 16 + a;
        float gg = 1.f / (1.f + __expf(-(gacc[a] + bg)));
        osh[aa][col] = gg * (ap[a] + ba) + (1.f - gg) * upd[aa][col];
    }
    __syncthreads();
    float f[16];
#pragma unroll
    for (int a = 0; a < 16; a++) f[a] = 0.f;
    for (int d = 0; d < 128; d++) {
        float wv = ow[d * HID + col];
#pragma unroll
        for (int a = 0; a < 16; a++) f[a] += osh[half * 16 + a][d] * wv;
    }
    float bo = ob[col];
#pragma unroll
    for (int a = 0; a < 16; a++)
        out[(size_t)(base + half * 16 + a) * HID + col] = f[a] + bo;
}

// ---------------- launch ----------------
extern "C" void kernel_launch(void* const* d_in, const int* in_sizes, int n_in,
                              void* d_out, int out_size) {
    const int* an = (const int*)d_in[0];
    const int* ei = (const int*)d_in[2];
    const float* ev = (const float*)d_in[3];
    const float* el = (const float*)d_in[4];
    const float* embed = (const float*)d_in[5];
    const float* rw1 = (const float*)d_in[6];
    const float* rb1 = (const float*)d_in[7];
    const float* rw2 = (const float*)d_in[8];
    const float* rb2 = (const float*)d_in[9];
    const float* tpw = (const float*)d_in[10];
    const float* tpb = (const float*)d_in[11];
    const float* mw1 = (const float*)d_in[12];
    const float* mb1 = (const float*)d_in[13];
    const float* mw2 = (const float*)d_in[14];
    const float* mb2 = (const float*)d_in[15];
    const float* win = (const float*)d_in[16];
    const float* bin = (const float*)d_in[17];
    const float* wout = (const float*)d_in[18];
    const float* bout = (const float*)d_in[19];
    const float* gw = (const float*)d_in[20];
    const float* gb = (const float*)d_in[21];
    const float* ow = (const float*)d_in[22];
    const float* obv = (const float*)d_in[23];
    float* out = (float*)d_out;

    const int* dst = ei + N_EDGES;

    megaA_kernel<<<1601, 256>>>(tpw, win, wout, rw1, rb1, rw2, rb2, dst);
    scan_kernel<<<1, 1024>>>();
    scatter_kernel<<<512, 256>>>(dst, ev, el);
    edge_agg_kernel<<<2048, 128>>>();
    tpupd_kernel<<<128, 256>>>(tpb, an, embed, mw1, mb1, mw2, mb2, bin);
    attn_mma_kernel<<<dim3(32, 4), 256>>>();
    epi_kernel<<<128, 256>>>(bout, gw, gb, ow, obv, out);
}

// round 16
// speedup vs baseline: 1.0456x; 1.0440x over previous
#include <cuda_runtime.h>
#include <cuda_bf16.h>
#include <math.h>
#include <stdint.h>

#define N_ATOMS 4096
#define N_EDGES 131072
#define EMBED 64
#define HID 128
#define TP_IN 1152
#define NBINS 2048
#define D_LO 0.4f
#define D_HI 6.0f

// ---------------- scratch ----------------
__device__ __align__(16) float g_pre[N_ATOMS * TP_IN];
__device__ __align__(16) float g_upd[N_ATOMS * HID];
__device__ __align__(16) float g_q[N_ATOMS * HID];
__device__ __align__(16) __nv_bfloat16 g_k16[N_ATOMS * HID];
__device__ __align__(16) __nv_bfloat16 g_v16[N_ATOMS * HID];
__device__ __align__(16) float g_att[N_ATOMS * HID];
__device__ __align__(16) float g_tpw[TP_IN * HID];
__device__ __align__(16) float g_wqkvT[HID * 3 * HID];
__device__ __align__(16) float g_woutT[HID * HID];
__device__ __align__(16) float g_radtab[(NBINS + 8) * HID];
__device__ __align__(16) float4 g_evp[N_EDGES];  // permuted edge payload {vx,vy,vz,d}
__device__ __align__(16) int g_count[N_ATOMS];   // zeroed by epi each launch
__device__ int g_offset[N_ATOMS + 1];
__device__ int g_cursor[N_ATOMS];

// ---------------- helpers ----------------
__device__ __forceinline__ void mma_tf32(float* d, const uint32_t* a, const uint32_t* b) {
    asm volatile(
        "mma.sync.aligned.m16n8k8.row.col.f32.tf32.tf32.f32 "
        "{%0,%1,%2,%3},{%4,%5,%6,%7},{%8,%9},{%0,%1,%2,%3};\n"
        : "+f"(d[0]), "+f"(d[1]), "+f"(d[2]), "+f"(d[3])
        : "r"(a[0]), "r"(a[1]), "r"(a[2]), "r"(a[3]), "r"(b[0]), "r"(b[1]));
}
__device__ __forceinline__ void mma_bf16(float* d, const uint32_t* a, const uint32_t* b) {
    asm volatile(
        "mma.sync.aligned.m16n8k16.row.col.f32.bf16.bf16.f32 "
        "{%0,%1,%2,%3},{%4,%5,%6,%7},{%8,%9},{%0,%1,%2,%3};\n"
        : "+f"(d[0]), "+f"(d[1]), "+f"(d[2]), "+f"(d[3])
        : "r"(a[0]), "r"(a[1]), "r"(a[2]), "r"(a[3]), "r"(b[0]), "r"(b[1]));
}
__device__ __forceinline__ uint32_t rna_bits(float x) {
    uint32_t r;
    asm("cvt.rna.tf32.f32 %0, %1;" : "=r"(r) : "f"(x));
    return r;
}
__device__ __forceinline__ float rna_tf32(float x) {
    return __uint_as_float(rna_bits(x));
}
__device__ __forceinline__ uint32_t packbf(float lo, float hi) {
    uint32_t r;
    asm("cvt.rn.bf16x2.f32 %0, %1, %2;" : "=r"(r) : "f"(hi), "f"(lo));
    return r;
}
__device__ __forceinline__ float fexp2(float x) {
    float r;
    asm("ex2.approx.ftz.f32 %0, %1;" : "=f"(r) : "f"(x));
    return r;
}
__device__ __forceinline__ void cp16(uint32_t dst, const void* src) {
    asm volatile("cp.async.cg.shared.global [%0], [%1], 16;\n" :: "r"(dst), "l"(src));
}
__device__ __forceinline__ void ldmatrix_x4(uint32_t* r, uint32_t addr) {
    asm volatile("ldmatrix.sync.aligned.m8n8.x4.shared.b16 {%0,%1,%2,%3}, [%4];"
                 : "=r"(r[0]), "=r"(r[1]), "=r"(r[2]), "=r"(r[3]) : "r"(addr));
}
__device__ __forceinline__ void ldmatrix_x4_trans(uint32_t* r, uint32_t addr) {
    asm volatile("ldmatrix.sync.aligned.m8n8.x4.trans.shared.b16 {%0,%1,%2,%3}, [%4];"
                 : "=r"(r[0]), "=r"(r[1]), "=r"(r[2]), "=r"(r[3]) : "r"(addr));
}
#define CP_COMMIT asm volatile("cp.async.commit_group;\n" ::: "memory")
#define CP_WAIT0  asm volatile("cp.async.wait_group 0;\n" ::: "memory")

// =============== mega kernel A: prep | radtab | hist (independent) ===========
__global__ void __launch_bounds__(256) megaA_kernel(
    const float* __restrict__ tpw, const float* __restrict__ win,
    const float* __restrict__ wout,
    const float* __restrict__ rw1, const float* __restrict__ rb1,
    const float* __restrict__ rw2, const float* __restrict__ rb2,
    const int* __restrict__ dst) {
    __shared__ float w1s[8 * 64];
    __shared__ float w2s[64 * 128];
    __shared__ float b1s[64];
    __shared__ float b2s[128];
    __shared__ float r1s[8][64];
    const int b = blockIdx.x;
    const int t = threadIdx.x;

    if (b < 576) {
        int i = b * 256 + t;
        int rp = i >> 7;
        int c = i & 127;
        int s = rp >> 7;
        int h = rp & 127;
        int row;
        if (s == 0)      row = h;
        else if (s <= 3) row = 128 + h * 3 + (s - 1);
        else             row = 512 + h * 5 + (s - 4);
        g_tpw[i] = rna_tf32(tpw[row * HID + c]);
    } else if (b < 768) {
        int i = (b - 576) * 256 + t;
        int d = i / 384, j = i % 384;
        g_wqkvT[i] = win[j * HID + d];
    } else if (b < 832) {
        int i = (b - 768) * 256 + t;
        int d = i >> 7, j = i & 127;
        g_woutT[i] = wout[j * HID + d];
    } else if (b < 1089) {       // radial table
        for (int i = t; i < 512; i += 256) w1s[i] = rw1[i];
        for (int i = t; i < 8192; i += 256) w2s[i] = rw2[i];
        if (t < 64) b1s[t] = rb1[t];
        if (t < 128) b2s[t] = rb2[t];
        __syncthreads();
        int w = t >> 5, lane = t & 31;
        int bin = (b - 832) * 8 + w;
        if (bin > NBINS) return;
        const float hstep = (D_HI - D_LO) / (float)NBINS;
        const float FP = 3.14159265358979323846f / 6.0f;
        float d = D_LO + bin * hstep;
        float cut = 0.5f * (cosf(d * FP) + 1.f) * (d < 6.0f ? 1.f : 0.f);
        float invd = cut / d;
        float rbf[8];
#pragma unroll
        for (int i = 0; i < 8; i++) rbf[i] = sinf(d * (FP * (i + 1))) * invd;
        float a0 = b1s[lane], a1 = b1s[lane + 32];
#pragma unroll
        for (int i = 0; i < 8; i++) {
            a0 += rbf[i] * w1s[i * 64 + lane];
            a1 += rbf[i] * w1s[i * 64 + lane + 32];
        }
        a0 = a0 / (1.f + __expf(-a0));
        a1 = a1 / (1.f + __expf(-a1));
        r1s[w][lane] = a0;
        r1s[w][lane + 32] = a1;
        __syncwarp();
        float r2[4];
#pragma unroll
        for (int k = 0; k < 4; k++) r2[k] = b2s[k * 32 + lane];
#pragma unroll 8
        for (int j = 0; j < 64; j++) {
            float rj = r1s[w][j];
#pragma unroll
            for (int k = 0; k < 4; k++) r2[k] += rj * w2s[j * 128 + k * 32 + lane];
        }
#pragma unroll
        for (int k = 0; k < 4; k++) {
            float v = r2[k];
            v = v / (1.f + __expf(-v));
            g_radtab[bin * HID + k * 32 + lane] = v;
        }
    } else {
        int i = (b - 1089) * 256 + t;
        if (i < N_EDGES) atomicAdd(&g_count[dst[i]], 1);
    }
}

// ---------------- hierarchical warp scan ----------------
__global__ void __launch_bounds__(1024) scan_kernel() {
    __shared__ int wsum[32];
    int t = threadIdx.x, lane = t & 31, wid = t >> 5;
    int4 v = *(const int4*)(g_count + t * 4);
    int s0 = v.x, s1 = s0 + v.y, s2 = s1 + v.z, s3 = s2 + v.w;
    int ws = s3;
#pragma unroll
    for (int off = 1; off < 32; off <<= 1) {
        int n = __shfl_up_sync(0xffffffffu, ws, off);
        if (lane >= off) ws += n;
    }
    if (lane == 31) wsum[wid] = ws;
    __syncthreads();
    if (wid == 0) {
        int x = wsum[lane];
#pragma unroll
        for (int off = 1; off < 32; off <<= 1) {
            int n = __shfl_up_sync(0xffffffffu, x, off);
            if (lane >= off) x += n;
        }
        wsum[lane] = x;
    }
    __syncthreads();
    int base = (wid ? wsum[wid - 1] : 0) + (ws - s3);
    g_offset[t * 4 + 1] = base + s0;
    g_offset[t * 4 + 2] = base + s1;
    g_offset[t * 4 + 3] = base + s2;
    g_offset[t * 4 + 4] = base + s3;
    g_cursor[t * 4 + 0] = base;
    g_cursor[t * 4 + 1] = base + s0;
    g_cursor[t * 4 + 2] = base + s1;
    g_cursor[t * 4 + 3] = base + s2;
    if (t == 0) g_offset[0] = 0;
}

// ---------------- scatter: permute full edge payload ----------------
__global__ void scatter_kernel(const int* __restrict__ dst,
                               const float* __restrict__ ev,
                               const float* __restrict__ el) {
    int i = blockIdx.x * blockDim.x + threadIdx.x;
    if (i < N_EDGES) {
        float vx = ev[i * 3 + 0];
        float vy = ev[i * 3 + 1];
        float vz = ev[i * 3 + 2];
        float d = el[i];
        int p = atomicAdd(&g_cursor[dst[i]], 1);
        g_evp[p] = make_float4(vx, vy, vz, d);
    }
}

// ------- edge aggregation: 2 warps per atom; contiguous payload loads -------
__global__ void __launch_bounds__(128) edge_agg_kernel() {
    __shared__ float red[2][4][9][32];
    int t = threadIdx.x;
    int w = t >> 5, lane = t & 31;
    int pair = w >> 1, h = w & 1;
    int atom = blockIdx.x * 2 + pair;
    int start = g_offset[atom];
    int end = g_offset[atom + 1];
    int n = end - start;
    int halfn = (n + 1) >> 1;
    int s0 = start + h * halfn;
    int e0 = min(end, s0 + halfn);

    float acc[4][9];
#pragma unroll
    for (int k = 0; k < 4; k++)
#pragma unroll
        for (int s = 0; s < 9; s++) acc[k][s] = 0.f;

    const float INV_H = (float)NBINS / (D_HI - D_LO);

    int idx = s0;
    for (; idx + 2 <= e0; idx += 2) {
        float4 p0v = __ldg(g_evp + idx);
        float4 p1v = __ldg(g_evp + idx + 1);
        float vx0 = p0v.x, vy0 = p0v.y, vz0 = p0v.z, d0 = p0v.w;
        float vx1 = p1v.x, vy1 = p1v.y, vz1 = p1v.z, d1 = p1v.w;

        float tt0 = (d0 - D_LO) * INV_H;
        float tt1 = (d1 - D_LO) * INV_H;
        int i00 = min(max((int)tt0, 0), NBINS - 1);
        int i01 = min(max((int)tt1, 0), NBINS - 1);
        float f0 = tt0 - (float)i00;
        float f1 = tt1 - (float)i01;
        const float* r0p = g_radtab + (size_t)i00 * HID;
        const float* r1p = g_radtab + (size_t)i01 * HID;

        float r0 = sqrtf(vx0 * vx0 + vy0 * vy0 + vz0 * vz0) + 1e-8f;
        float r1 = sqrtf(vx1 * vx1 + vy1 * vy1 + vz1 * vz1) + 1e-8f;
        float iv0 = 1.f / r0, iv1 = 1.f / r1;
        float x0 = vx0 * iv0, y0 = vy0 * iv0, z0 = vz0 * iv0;
        float x1 = vx1 * iv1, y1 = vy1 * iv1, z1 = vz1 * iv1;
        float sh0[9], sh1[9];
        sh0[0] = 1.f; sh0[1] = y0; sh0[2] = z0; sh0[3] = x0;
        sh0[4] = 3.f * z0 * z0 - 1.f; sh0[5] = x0 * z0; sh0[6] = y0 * z0;
        sh0[7] = x0 * y0; sh0[8] = x0 * x0 - y0 * y0;
        sh1[0] = 1.f; sh1[1] = y1; sh1[2] = z1; sh1[3] = x1;
        sh1[4] = 3.f * z1 * z1 - 1.f; sh1[5] = x1 * z1; sh1[6] = y1 * z1;
        sh1[7] = x1 * y1; sh1[8] = x1 * x1 - y1 * y1;

#pragma unroll
        for (int k = 0; k < 4; k++) {
            int c = k * 32 + lane;
            float lo0 = r0p[c], hi0 = r0p[c + HID];
            float lo1 = r1p[c], hi1 = r1p[c + HID];
            float ra0 = fmaf(f0, hi0 - lo0, lo0);
            float ra1 = fmaf(f1, hi1 - lo1, lo1);
#pragma unroll
            for (int s = 0; s < 9; s++)
                acc[k][s] += ra0 * sh0[s] + ra1 * sh1[s];
        }
    }
    if (idx < e0) {
        float4 pv = __ldg(g_evp + idx);
        float vx = pv.x, vy = pv.y, vz = pv.z, d = pv.w;
        float r = sqrtf(vx * vx + vy * vy + vz * vz) + 1e-8f;
        float inv = 1.f / r;
        float x = vx * inv, y = vy * inv, z = vz * inv;
        float sh[9];
        sh[0] = 1.f; sh[1] = y; sh[2] = z; sh[3] = x;
        sh[4] = 3.f * z * z - 1.f; sh[5] = x * z; sh[6] = y * z;
        sh[7] = x * y; sh[8] = x * x - y * y;
        float tt = (d - D_LO) * INV_H;
        int i0 = min(max((int)tt, 0), NBINS - 1);
        float f = tt - (float)i0;
        const float* r0p = g_radtab + (size_t)i0 * HID;
#pragma unroll
        for (int k = 0; k < 4; k++) {
            int c = k * 32 + lane;
            float lo = r0p[c], hi = r0p[c + HID];
            float ra = fmaf(f, hi - lo, lo);
#pragma unroll
            for (int s = 0; s < 9; s++) acc[k][s] += ra * sh[s];
        }
    }

    if (h == 1) {
#pragma unroll
        for (int k = 0; k < 4; k++)
#pragma unroll
            for (int s = 0; s < 9; s++) red[pair][k][s][lane] = acc[k][s];
    }
    __syncthreads();
    if (h == 0) {
#pragma unroll
        for (int k = 0; k < 4; k++)
#pragma unroll
            for (int s = 0; s < 9; s++) {
                float v = acc[k][s] + red[pair][k][s][lane];
                g_pre[(size_t)atom * TP_IN + s * 128 + k * 32 + lane] = v;
            }
    }
}

// ======= FUSED: tp-GEMM (tf32 mma, K-chunk 32) -> upd MLP -> qkv ============
// Dynamic smem: As 2x(32x36)=9216B | Bs 2x(32x136)=34816B | comb 24576B | ans.
// t1 (16KB, phase 2) aliases the As/Bs region. Total 68736 B.
__global__ void __launch_bounds__(256) tpupd_kernel(
    const float* __restrict__ tpb,
    const int* __restrict__ an, const float* __restrict__ embed,
    const float* __restrict__ mw1, const float* __restrict__ mb1,
    const float* __restrict__ mw2, const float* __restrict__ mb2,
    const float* __restrict__ bqkv) {
    extern __shared__ __align__(16) char sraw[];
    float* As = (float*)sraw;                    // 2 x 1152 floats
    float* Bs = (float*)(sraw + 9216);           // 2 x 4352 floats
    float* t1 = (float*)sraw;                    // 32 x 128 (phase 2 alias)
    float* comb = (float*)(sraw + 44032);        // 32 x 192
    int* ans = (int*)(sraw + 68608);

    const int t = threadIdx.x;
    const int warp = t >> 5, lane = t & 31;
    const int g = lane >> 2, tg = lane & 3;
    const int rows0 = blockIdx.x * 32;
    const int rloc = (warp & 1) * 16;
    const int c0 = (warp >> 1) * 32;

    uint32_t as_base = (uint32_t)__cvta_generic_to_shared(As);
    uint32_t bs_base = (uint32_t)__cvta_generic_to_shared(Bs);

    if (t < 32) ans[t] = an[rows0 + t];
    __syncthreads();
    for (int i = t; i < 2048; i += 256) {
        int a = i >> 6, d = i & 63;
        comb[a * 192 + d] = embed[ans[a] * 64 + d];
    }

    float C[4][4];
#pragma unroll
    for (int nn = 0; nn < 4; nn++)
#pragma unroll
        for (int i = 0; i < 4; i++) C[nn][i] = 0.f;

    // prologue: K-chunk 0 (A: 32x32, B: 32x128)
    {
        int r = t >> 3, ch = (t & 7) * 4;
        cp16(as_base + (r * 36 + ch) * 4, g_pre + (size_t)(rows0 + r) * TP_IN + ch);
    }
#pragma unroll
    for (int i = t; i < 1024; i += 256) {
        int kr = i >> 5, c = (i & 31) * 4;
        cp16(bs_base + (kr * 136 + c) * 4, g_tpw + (size_t)kr * HID + c);
    }
    CP_COMMIT;

    for (int kc = 0; kc < 36; kc++) {
        CP_WAIT0;
        __syncthreads();
        int buf = kc & 1;
        if (kc + 1 < 36) {
            int nb = buf ^ 1;
            {
                int r = t >> 3, ch = (t & 7) * 4;
                cp16(as_base + (nb * 1152 + r * 36 + ch) * 4,
                     g_pre + (size_t)(rows0 + r) * TP_IN + (kc + 1) * 32 + ch);
            }
#pragma unroll
            for (int i = t; i < 1024; i += 256) {
                int kr = i >> 5, c = (i & 31) * 4;
                cp16(bs_base + (nb * 4352 + kr * 136 + c) * 4,
                     g_tpw + (size_t)((kc + 1) * 32 + kr) * HID + c);
            }
            CP_COMMIT;
        }
#pragma unroll
        for (int k8 = 0; k8 < 4; k8++) {
            int k0 = k8 * 8;
            uint32_t a4[4];
            a4[0] = rna_bits(As[buf * 1152 + (rloc + g) * 36 + k0 + tg]);
            a4[1] = rna_bits(As[buf * 1152 + (rloc + g + 8) * 36 + k0 + tg]);
            a4[2] = rna_bits(As[buf * 1152 + (rloc + g) * 36 + k0 + tg + 4]);
            a4[3] = rna_bits(As[buf * 1152 + (rloc + g + 8) * 36 + k0 + tg + 4]);
#pragma unroll
            for (int nn = 0; nn < 4; nn++) {
                uint32_t b[2];
                b[0] = __float_as_uint(Bs[buf * 4352 + (k0 + tg) * 136 + c0 + nn * 8 + g]);
                b[1] = __float_as_uint(Bs[buf * 4352 + (k0 + tg + 4) * 136 + c0 + nn * 8 + g]);
                mma_tf32(C[nn], a4, b);
            }
        }
        // trailing sync removed: next iteration's head sync orders buffer reuse
    }

    {
        int a0 = rloc + g, a1 = a0 + 8;
        int gr0 = rows0 + a0, gr1 = rows0 + a1;
        float deg0 = (float)(g_offset[gr0 + 1] - g_offset[gr0]);
        float deg1 = (float)(g_offset[gr1 + 1] - g_offset[gr1]);
#pragma unroll
        for (int nn = 0; nn < 4; nn++) {
            int col = c0 + nn * 8 + 2 * tg;
            float b0 = tpb[col], b1 = tpb[col + 1];
            comb[a0 * 192 + 64 + col] = C[nn][0] + deg0 * b0;
            comb[a0 * 192 + 64 + col + 1] = C[nn][1] + deg0 * b1;
            comb[a1 * 192 + 64 + col] = C[nn][2] + deg1 * b0;
            comb[a1 * 192 + 64 + col + 1] = C[nn][3] + deg1 * b1;
        }
    }
    __syncthreads();

    const int col = t & 127;
    const int half = t >> 7;
    float acc[16];
#pragma unroll
    for (int a = 0; a < 16; a++) acc[a] = 0.f;
    for (int d = 0; d < 192; d++) {
        float wv = mw1[d * HID + col];
#pragma unroll
        for (int a = 0; a < 16; a++) acc[a] += comb[(half * 16 + a) * 192 + d] * wv;
    }
    float b1v = mb1[col];
#pragma unroll
    for (int a = 0; a < 16; a++) {
        float v = acc[a] + b1v;
        t1[(half * 16 + a) * 128 + col] = v / (1.f + __expf(-v));
    }
    __syncthreads();
#pragma unroll
    for (int a = 0; a < 16; a++) acc[a] = 0.f;
    for (int d = 0; d < 128; d++) {
        float wv = mw2[d * HID + col];
#pragma unroll
        for (int a = 0; a < 16; a++) acc[a] += t1[(half * 16 + a) * 128 + d] * wv;
    }
    float b2v = mb2[col];
#pragma unroll
    for (int a = 0; a < 16; a++) {
        int aa = half * 16 + a;
        float v = acc[a] + b2v;
        comb[aa * 128 + col] = v;
        g_upd[(size_t)(rows0 + aa) * HID + col] = v;
    }
    __syncthreads();

    float* upds = comb;
#pragma unroll
    for (int cb = 0; cb < 3; cb++) {
        float q[16];
#pragma unroll
        for (int a = 0; a < 16; a++) q[a] = 0.f;
        for (int d = 0; d < 128; d++) {
            float wv = g_wqkvT[d * 384 + cb * 128 + col];
#pragma unroll
            for (int a = 0; a < 16; a++) q[a] += upds[(half * 16 + a) * 128 + d] * wv;
        }
        float bb = bqkv[cb * 128 + col];
#pragma unroll
        for (int a = 0; a < 16; a++) {
            int aa = half * 16 + a;
            float s = q[a] + bb;
            size_t row = (size_t)(rows0 + aa) * HID;
            if (cb == 0)      g_q[row + col] = s;
            else if (cb == 1) g_k16[row + col] = __float2bfloat16_rn(s);
            else              g_v16[row + col] = __float2bfloat16_rn(s);
        }
    }
}

// ---------------- bf16 mma flash attention — 128-key tiles, single wave -----
// K frags via ldmatrix.x4 (non-trans), V via ldmatrix.x4.trans; one sync/tile.
__global__ void __launch_bounds__(256) attn_mma_kernel() {
    __shared__ __align__(16) __nv_bfloat16 Ks[2][128 * 40];
    __shared__ __align__(16) __nv_bfloat16 Vs[2][128 * 40];
    const int t = threadIdx.x;
    const int warp = t >> 5, lane = t & 31;
    const int g = lane >> 2, tg = lane & 3;
    const int head = blockIdx.y;
    const int q0 = blockIdx.x * 128 + warp * 16;
    const float SC = 0.17677669529663687f * 1.4426950408889634f;

    uint32_t ks_base = (uint32_t)__cvta_generic_to_shared(Ks);
    uint32_t vs_base = (uint32_t)__cvta_generic_to_shared(Vs);

    uint32_t qb[2][4];
#pragma unroll
    for (int kk2 = 0; kk2 < 2; kk2++) {
        const float* qp = g_q + (size_t)(q0 + g) * HID + head * 32 + kk2 * 16;
        const float* qp8 = qp + 8 * HID;
        float2 f0 = *(const float2*)(qp + 2 * tg);
        float2 f1 = *(const float2*)(qp8 + 2 * tg);
        float2 f2 = *(const float2*)(qp + 2 * tg + 8);
        float2 f3 = *(const float2*)(qp8 + 2 * tg + 8);
        qb[kk2][0] = packbf(f0.x * SC, f0.y * SC);
        qb[kk2][1] = packbf(f1.x * SC, f1.y * SC);
        qb[kk2][2] = packbf(f2.x * SC, f2.y * SC);
        qb[kk2][3] = packbf(f3.x * SC, f3.y * SC);
    }

    float O[4][4];
#pragma unroll
    for (int nn = 0; nn < 4; nn++)
#pragma unroll
        for (int i = 0; i < 4; i++) O[nn][i] = 0.f;
    float m0 = -1e30f, m1 = -1e30f, l0 = 0.f, l1 = 0.f;

#pragma unroll
    for (int i = t; i < 1024; i += 256) {
        int key = i >> 3, part = i & 7;
        int kv = part >> 2;
        int ch = (part & 3) * 16;
        const char* src = (const char*)(kv ? g_v16 : g_k16) +
                          (size_t)key * 256 + head * 64 + ch;
        uint32_t dst = (kv ? vs_base : ks_base) + key * 80 + ch;
        cp16(dst, src);
    }
    CP_COMMIT;

    const int klane_row = lane & 7;
    const int klane_khalf = (lane >> 3) & 1;
    const int klane_nn = lane >> 4;
    const int vlane_row = lane & 15;
    const int vlane_nn = lane >> 4;

    for (int kt = 0; kt < 32; kt++) {
        CP_WAIT0;
        __syncthreads();
        int buf = kt & 1;
        if (kt + 1 < 32) {
            int nb = buf ^ 1;
#pragma unroll
            for (int i = t; i < 1024; i += 256) {
                int key = i >> 3, part = i & 7;
                int kv = part >> 2;
                int ch = (part & 3) * 16;
                const char* src = (const char*)(kv ? g_v16 : g_k16) +
                                  (size_t)((kt + 1) * 128 + key) * 256 + head * 64 + ch;
                uint32_t dst = (kv ? vs_base : ks_base) + nb * 10240 + key * 80 + ch;
                cp16(dst, src);
            }
            CP_COMMIT;
        }

        float S[16][4];
#pragma unroll
        for (int nn = 0; nn < 16; nn++)
#pragma unroll
            for (int i = 0; i < 4; i++) S[nn][i] = 0.f;
        uint32_t kaddr_base = ks_base + buf * 10240 +
                              (klane_row + klane_nn * 8) * 80 + klane_khalf * 16;
#pragma unroll
        for (int kk2 = 0; kk2 < 2; kk2++) {
#pragma unroll
            for (int nn2 = 0; nn2 < 8; nn2++) {
                uint32_t b4[4];
                ldmatrix_x4(b4, kaddr_base + nn2 * (16 * 80) + kk2 * 32);
                mma_bf16(S[2 * nn2], qb[kk2], b4);
                mma_bf16(S[2 * nn2 + 1], qb[kk2], b4 + 2);
            }
        }

        float mx0 = fmaxf(S[0][0], S[0][1]);
        float mx1 = fmaxf(S[0][2], S[0][3]);
#pragma unroll
        for (int nn = 1; nn < 16; nn++) {
            mx0 = fmaxf(mx0, fmaxf(S[nn][0], S[nn][1]));
            mx1 = fmaxf(mx1, fmaxf(S[nn][2], S[nn][3]));
        }
        mx0 = fmaxf(mx0, __shfl_xor_sync(0xffffffffu, mx0, 1));
        mx0 = fmaxf(mx0, __shfl_xor_sync(0xffffffffu, mx0, 2));
        mx1 = fmaxf(mx1, __shfl_xor_sync(0xffffffffu, mx1, 1));
        mx1 = fmaxf(mx1, __shfl_xor_sync(0xffffffffu, mx1, 2));
        float nm0 = fmaxf(m0, mx0), nm1 = fmaxf(m1, mx1);
        float c0 = fexp2(m0 - nm0), c1 = fexp2(m1 - nm1);
        m0 = nm0; m1 = nm1;
        l0 *= c0; l1 *= c1;
#pragma unroll
        for (int nn = 0; nn < 4; nn++) {
            O[nn][0] *= c0; O[nn][1] *= c0;
            O[nn][2] *= c1; O[nn][3] *= c1;
        }
#pragma unroll
        for (int nn = 0; nn < 16; nn++) {
            float p0 = fexp2(S[nn][0] - m0);
            float p1 = fexp2(S[nn][1] - m0);
            float p2 = fexp2(S[nn][2] - m1);
            float p3 = fexp2(S[nn][3] - m1);
            l0 += p0 + p1;
            l1 += p2 + p3;
            S[nn][0] = p0; S[nn][1] = p1; S[nn][2] = p2; S[nn][3] = p3;
        }

        uint32_t vaddr_base = vs_base + buf * 10240 + vlane_row * 80 + vlane_nn * 16;
#pragma unroll
        for (int kkv = 0; kkv < 8; kkv++) {
            uint32_t a[4];
            a[0] = packbf(S[2 * kkv][0], S[2 * kkv][1]);
            a[1] = packbf(S[2 * kkv][2], S[2 * kkv][3]);
            a[2] = packbf(S[2 * kkv + 1][0], S[2 * kkv + 1][1]);
            a[3] = packbf(S[2 * kkv + 1][2], S[2 * kkv + 1][3]);
            uint32_t rowaddr = vaddr_base + kkv * (16 * 80);
#pragma unroll
            for (int nn2 = 0; nn2 < 2; nn2++) {
                uint32_t b4[4];
                ldmatrix_x4_trans(b4, rowaddr + nn2 * 32);
                mma_bf16(O[2 * nn2], a, b4);
                mma_bf16(O[2 * nn2 + 1], a, b4 + 2);
            }
        }
        // trailing sync removed: next iteration's head sync orders buffer reuse
    }

    l0 += __shfl_xor_sync(0xffffffffu, l0, 1);
    l0 += __shfl_xor_sync(0xffffffffu, l0, 2);
    l1 += __shfl_xor_sync(0xffffffffu, l1, 1);
    l1 += __shfl_xor_sync(0xffffffffu, l1, 2);
    float i0 = 1.f / l0, i1 = 1.f / l1;
#pragma unroll
    for (int nn = 0; nn < 4; nn++) {
        *(float2*)(g_att + (size_t)(q0 + g) * HID + head * 32 + nn * 8 + 2 * tg) =
            make_float2(O[nn][0] * i0, O[nn][1] * i0);
        *(float2*)(g_att + (size_t)(q0 + g + 8) * HID + head * 32 + nn * 8 + 2 * tg) =
            make_float2(O[nn][2] * i1, O[nn][3] * i1);
    }
}

// ---------------- epilogue: 128 blocks x 256 thr x 32 atoms (single wave) ---
__global__ void __launch_bounds__(256) epi_kernel(
    const float* __restrict__ bout_att,
    const float* __restrict__ gw, const float* __restrict__ gb,
    const float* __restrict__ ow, const float* __restrict__ ob,
    float* __restrict__ out) {
    __shared__ float att[32][128];
    __shared__ float upd[32][128];
    __shared__ float osh[32][128];
    int t = threadIdx.x;
    int base = blockIdx.x * 32;
    for (int i = t; i < 4096; i += 256) {
        int a = i >> 7, d = i & 127;
        att[a][d] = g_att[(size_t)(base + a) * HID + d];
        upd[a][d] = g_upd[(size_t)(base + a) * HID + d];
    }
    if (t < 32) g_count[base + t] = 0;
    __syncthreads();
    const int col = t & 127;
    const int half = t >> 7;
    float ap[16];
#pragma unroll
    for (int a = 0; a < 16; a++) ap[a] = 0.f;
    for (int d = 0; d < 128; d++) {
        float wv = g_woutT[d * HID + col];
#pragma unroll
        for (int a = 0; a < 16; a++) ap[a] += att[half * 16 + a][d] * wv;
    }
    float ba = bout_att[col];
    float gacc[16];
#pragma unroll
    for (int a = 0; a < 16; a++) gacc[a] = 0.f;
    for (int d = 0; d < 128; d++) {
        float wv = gw[d * HID + col];
#pragma unroll
        for (int a = 0; a < 16; a++) gacc[a] += upd[half * 16 + a][d] * wv;
    }
    float bg = gb[col];
#pragma unroll
    for (int a = 0; a < 16; a++) {
        int aa = half * 16 + a;
        float gg = 1.f / (1.f + __expf(-(gacc[a] + bg)));
        osh[aa][col] = gg * (ap[a] + ba) + (1.f - gg) * upd[aa][col];
    }
    __syncthreads();
    float f[16];
#pragma unroll
    for (int a = 0; a < 16; a++) f[a] = 0.f;
    for (int d = 0; d < 128; d++) {
        float wv = ow[d * HID + col];
#pragma unroll
        for (int a = 0; a < 16; a++) f[a] += osh[half * 16 + a][d] * wv;
    }
    float bo = ob[col];
#pragma unroll
    for (int a = 0; a < 16; a++)
        out[(size_t)(base + half * 16 + a) * HID + col] = f[a] + bo;
}

// ---------------- launch ----------------
extern "C" void kernel_launch(void* const* d_in, const int* in_sizes, int n_in,
                              void* d_out, int out_size) {
    const int* an = (const int*)d_in[0];
    const int* ei = (const int*)d_in[2];
    const float* ev = (const float*)d_in[3];
    const float* el = (const float*)d_in[4];
    const float* embed = (const float*)d_in[5];
    const float* rw1 = (const float*)d_in[6];
    const float* rb1 = (const float*)d_in[7];
    const float* rw2 = (const float*)d_in[8];
    const float* rb2 = (const float*)d_in[9];
    const float* tpw = (const float*)d_in[10];
    const float* tpb = (const float*)d_in[11];
    const float* mw1 = (const float*)d_in[12];
    const float* mb1 = (const float*)d_in[13];
    const float* mw2 = (const float*)d_in[14];
    const float* mb2 = (const float*)d_in[15];
    const float* win = (const float*)d_in[16];
    const float* bin = (const float*)d_in[17];
    const float* wout = (const float*)d_in[18];
    const float* bout = (const float*)d_in[19];
    const float* gw = (const float*)d_in[20];
    const float* gb = (const float*)d_in[21];
    const float* ow = (const float*)d_in[22];
    const float* obv = (const float*)d_in[23];
    float* out = (float*)d_out;

    const int* dst = ei + N_EDGES;

    cudaFuncSetAttribute(tpupd_kernel,
                         cudaFuncAttributeMaxDynamicSharedMemorySize, 68736);

    megaA_kernel<<<1601, 256>>>(tpw, win, wout, rw1, rb1, rw2, rb2, dst);
    scan_kernel<<<1, 1024>>>();
    scatter_kernel<<<512, 256>>>(dst, ev, el);
    edge_agg_kernel<<<2048, 128>>>();
    tpupd_kernel<<<128, 256, 68736>>>(tpb, an, embed, mw1, mb1, mw2, mb2, bin);
    attn_mma_kernel<<<dim3(32, 4), 256>>>();
    epi_kernel<<<128, 256>>>(bout, gw, gb, ow, obv, out);
}